// round 1
// baseline (speedup 1.0000x reference)
#include <cuda_runtime.h>
#include <math.h>

#define NN   50000
#define EE   800000
#define ETOT (EE + NN)      // 850000 edges incl. self loops
#define HID  128
#define HH   4
#define CC   32
#define GG   16
#define NEG  0.2f
#define EPSV 1e-5f

// ---------------- scratch (device globals; no runtime allocation) ----------
__device__ float g_h0[NN * HID];        // GEMM output / message source
__device__ float g_h1[NN * HID];        // layer feature buffer (agg -> BN -> next input)
__device__ float g_as[NN * HH];
__device__ float g_ad[NN * HH];
__device__ float g_e[HH * ETOT];        // per-edge-head e, later reused for w=exp(e-max)
__device__ int   g_cnt[NN];
__device__ int   g_cur[NN];
__device__ int   g_incl[NN];
__device__ int   g_rowptr[NN + 1];
__device__ int   g_col[ETOT];           // src per CSR slot
__device__ int   g_dstc[ETOT];          // dst per CSR slot
__device__ int   g_bsum[64];
__device__ float g_bnsum[HID], g_bnsq[HID], g_mean[HID], g_rstd[HID];
__device__ float g_pool[GG * HID];
__device__ int   g_gcnt[GG];

// ---------------- CSR build -------------------------------------------------
__global__ void k_zero_csr() {
    int i = blockIdx.x * blockDim.x + threadIdx.x;
    if (i < NN) { g_cnt[i] = 0; g_cur[i] = 0; }
}

__global__ void k_hist(const int* __restrict__ ei) {
    int e = blockIdx.x * blockDim.x + threadIdx.x;
    if (e >= ETOT) return;
    int d = (e < EE) ? ei[EE + e] : (e - EE);
    atomicAdd(&g_cnt[d], 1);
}

__global__ void k_scan_block() {
    __shared__ int s[1024];
    int i = blockIdx.x * 1024 + threadIdx.x;
    int v = (i < NN) ? g_cnt[i] : 0;
    s[threadIdx.x] = v;
    __syncthreads();
    for (int off = 1; off < 1024; off <<= 1) {
        int t = (threadIdx.x >= off) ? s[threadIdx.x - off] : 0;
        __syncthreads();
        s[threadIdx.x] += t;
        __syncthreads();
    }
    if (i < NN) g_incl[i] = s[threadIdx.x];
    if (threadIdx.x == 1023) g_bsum[blockIdx.x] = s[1023];
}

__global__ void k_scan_sums() {
    if (threadIdx.x == 0 && blockIdx.x == 0) {
        int nb = (NN + 1023) / 1024;
        int run = 0;
        for (int b = 0; b < nb; b++) { int t = g_bsum[b]; g_bsum[b] = run; run += t; }
    }
}

__global__ void k_rowptr() {
    int i = blockIdx.x * blockDim.x + threadIdx.x;
    if (i < NN) g_rowptr[i] = g_incl[i] - g_cnt[i] + g_bsum[i >> 10];
    if (i == 0) g_rowptr[NN] = ETOT;
}

__global__ void k_scatter(const int* __restrict__ ei) {
    int e = blockIdx.x * blockDim.x + threadIdx.x;
    if (e >= ETOT) return;
    int s, d;
    if (e < EE) { s = ei[e]; d = ei[EE + e]; }
    else        { s = e - EE; d = s; }
    int pos = g_rowptr[d] + atomicAdd(&g_cur[d], 1);
    g_col[pos]  = s;
    g_dstc[pos] = d;
}

// ---------------- GEMMs -----------------------------------------------------
// layer 0: [N,5] @ [5,128] -> g_h0
__global__ void k_gemm0(const float* __restrict__ X, const float* __restrict__ W0) {
    __shared__ float w[5 * HID];
    int tid = threadIdx.x;   // 128
    for (int i = tid; i < 5 * HID; i += 128) w[i] = W0[i];
    __syncthreads();
    int r0 = blockIdx.x * 64;
    for (int rr = 0; rr < 64; rr++) {
        int r = r0 + rr;
        if (r >= NN) break;
        float a = 0.f;
#pragma unroll
        for (int k = 0; k < 5; k++) a += X[r * 5 + k] * w[k * HID + tid];
        g_h0[r * HID + tid] = a;
    }
}

// layers 1..3: g_h1[N,128] @ B[128,128] -> g_h0. 64x128 tile, 8x4 microtile.
__global__ void k_gemm128(const float* __restrict__ B) {
    __shared__ float As[8][64];
    __shared__ float Bs[8][128];
    int tid  = threadIdx.x;     // 256
    int row0 = blockIdx.x * 64;
    int tcol = tid & 31;
    int trow = tid >> 5;
    float acc[8][4];
#pragma unroll
    for (int i = 0; i < 8; i++)
#pragma unroll
        for (int j = 0; j < 4; j++) acc[i][j] = 0.f;

    for (int k0 = 0; k0 < 128; k0 += 8) {
#pragma unroll
        for (int e = tid; e < 512; e += 256) {
            int r = e >> 3, k = e & 7;
            int row = row0 + r;
            As[k][r] = (row < NN) ? g_h1[row * HID + k0 + k] : 0.f;
        }
#pragma unroll
        for (int e = tid; e < 1024; e += 256) {
            int k = e >> 7, nn = e & 127;
            Bs[k][nn] = B[(k0 + k) * HID + nn];
        }
        __syncthreads();
#pragma unroll
        for (int k = 0; k < 8; k++) {
            float4 a0 = *(const float4*)&As[k][trow * 8];
            float4 a1 = *(const float4*)&As[k][trow * 8 + 4];
            float4 b4 = *(const float4*)&Bs[k][tcol * 4];
            float av[8] = {a0.x, a0.y, a0.z, a0.w, a1.x, a1.y, a1.z, a1.w};
            float bv[4] = {b4.x, b4.y, b4.z, b4.w};
#pragma unroll
            for (int i = 0; i < 8; i++)
#pragma unroll
                for (int j = 0; j < 4; j++) acc[i][j] += av[i] * bv[j];
        }
        __syncthreads();
    }
#pragma unroll
    for (int i = 0; i < 8; i++) {
        int row = row0 + trow * 8 + i;
        if (row < NN) {
            float4 v = make_float4(acc[i][0], acc[i][1], acc[i][2], acc[i][3]);
            *(float4*)&g_h0[row * HID + tcol * 4] = v;
        }
    }
}

// ---------------- attention -------------------------------------------------
// per (node, head) dot of h with att vectors. 2 nodes per block of 256.
__global__ void k_alpha(const float* __restrict__ asrc, const float* __restrict__ adst) {
    int n = blockIdx.x * 2 + (threadIdx.x >> 7);
    if (n >= NN) return;
    int t = threadIdx.x & 127;
    int hh = t >> 5, lane = t & 31;
    float v  = g_h0[n * HID + t];
    float s1 = v * asrc[t];
    float s2 = v * adst[t];
#pragma unroll
    for (int o = 16; o; o >>= 1) {
        s1 += __shfl_xor_sync(0xffffffffu, s1, o);
        s2 += __shfl_xor_sync(0xffffffffu, s2, o);
    }
    if (lane == 0) { g_as[n * HH + hh] = s1; g_ad[n * HH + hh] = s2; }
}

// e = leaky_relu(as[src]+ad[dst]) per head; layout [H][ETOT] for coalesced passes
__global__ void k_edge_e() {
    int pos = blockIdx.x * blockDim.x + threadIdx.x;
    if (pos >= ETOT) return;
    int s = g_col[pos], d = g_dstc[pos];
#pragma unroll
    for (int hh = 0; hh < HH; hh++) {
        float a = g_as[s * HH + hh] + g_ad[d * HH + hh];
        g_e[hh * ETOT + pos] = (a > 0.f) ? a : NEG * a;
    }
}

// one warp per (node, head): exact segment softmax + weighted gather, lane=channel
__global__ void k_agg(const float* __restrict__ bias_l) {
    int gw   = blockIdx.x * (blockDim.x >> 5) + (threadIdx.x >> 5);
    int lane = threadIdx.x & 31;
    if (gw >= NN * HH) return;
    int n = gw >> 2, hh = gw & 3;
    int beg = g_rowptr[n], end = g_rowptr[n + 1];
    int ebase = hh * ETOT;

    float m = -1e30f;
    for (int i = beg + lane; i < end; i += 32) m = fmaxf(m, g_e[ebase + i]);
#pragma unroll
    for (int o = 16; o; o >>= 1) m = fmaxf(m, __shfl_xor_sync(0xffffffffu, m, o));

    float sum = 0.f;
    for (int i = beg + lane; i < end; i += 32) {
        float w = __expf(g_e[ebase + i] - m);
        sum += w;
        g_e[ebase + i] = w;
    }
#pragma unroll
    for (int o = 16; o; o >>= 1) sum += __shfl_xor_sync(0xffffffffu, sum, o);
    float inv = 1.f / (sum + 1e-16f);
    __syncwarp();

    float acc = 0.f;
    int hc = hh * CC + lane;
    for (int i = beg; i < end; i++) {
        float w = g_e[ebase + i];     // broadcast
        int   s = g_col[i];           // broadcast
        acc += w * g_h0[s * HID + hc];  // coalesced 128B row
    }
    g_h1[n * HID + hc] = acc * inv + bias_l[hc];
}

// ---------------- batchnorm + silu ------------------------------------------
__global__ void k_bnzero() {
    int t = threadIdx.x;
    if (t < HID) { g_bnsum[t] = 0.f; g_bnsq[t] = 0.f; }
}

__global__ void k_bnred() {
    __shared__ float ss[256], sq[256];
    int col = threadIdx.x & 127;
    int rp  = threadIdx.x >> 7;
    float s = 0.f, q = 0.f;
    for (int r = blockIdx.x * 2 + rp; r < NN; r += gridDim.x * 2) {
        float v = g_h1[r * HID + col];
        s += v; q += v * v;
    }
    ss[threadIdx.x] = s; sq[threadIdx.x] = q;
    __syncthreads();
    if (threadIdx.x < 128) {
        atomicAdd(&g_bnsum[col], ss[threadIdx.x] + ss[threadIdx.x + 128]);
        atomicAdd(&g_bnsq[col],  sq[threadIdx.x] + sq[threadIdx.x + 128]);
    }
}

__global__ void k_bnstats() {
    int t = threadIdx.x;
    if (t < HID) {
        float mean = g_bnsum[t] / (float)NN;
        float var  = g_bnsq[t] / (float)NN - mean * mean;
        g_mean[t] = mean;
        g_rstd[t] = rsqrtf(var + EPSV);
    }
}

__global__ void k_bnapply(const float* __restrict__ gamma, const float* __restrict__ beta) {
    int idx = blockIdx.x * blockDim.x + threadIdx.x;
    if (idx >= NN * HID) return;
    int c = idx & 127;
    float v = g_h1[idx];
    float y = (v - g_mean[c]) * g_rstd[c] * gamma[c] + beta[c];
    g_h1[idx] = y / (1.f + __expf(-y));
}

// ---------------- pooling + MLP ---------------------------------------------
__global__ void k_poolzero() {
    int i = blockIdx.x * blockDim.x + threadIdx.x;
    if (i < GG * HID) g_pool[i] = 0.f;
    if (i >= GG * HID && i < GG * HID + GG) g_gcnt[i - GG * HID] = 0;
}

__global__ void k_gcnt(const int* __restrict__ batch) {
    __shared__ int sc[GG];
    if (threadIdx.x < GG) sc[threadIdx.x] = 0;
    __syncthreads();
    int i = blockIdx.x * blockDim.x + threadIdx.x;
    if (i < NN) atomicAdd(&sc[batch[i]], 1);
    __syncthreads();
    if (threadIdx.x < GG && sc[threadIdx.x]) atomicAdd(&g_gcnt[threadIdx.x], sc[threadIdx.x]);
}

// batch is sorted -> running accumulator, atomic only at segment boundaries
__global__ void k_pool(const int* __restrict__ batch) {
    int col = threadIdx.x;     // 128
    int r0  = blockIdx.x * 256;
    if (r0 >= NN) return;
    int rend = min(r0 + 256, NN);
    int cur  = batch[r0];
    float acc = 0.f;
    for (int r = r0; r < rend; r++) {
        int g = batch[r];
        if (g != cur) { atomicAdd(&g_pool[cur * HID + col], acc); acc = 0.f; cur = g; }
        acc += g_h1[r * HID + col];
    }
    atomicAdd(&g_pool[cur * HID + col], acc);
}

__global__ void k_mlp(const float* __restrict__ fc1w, const float* __restrict__ fc1b,
                      const float* __restrict__ fc2w, const float* __restrict__ fc2b,
                      float* __restrict__ out) {
    __shared__ float pm[GG * HID];
    __shared__ float z[GG * 64];
    int tid = threadIdx.x;   // 512
    for (int i = tid; i < GG * HID; i += 512) {
        int g = i >> 7;
        pm[i] = g_pool[i] / fmaxf((float)g_gcnt[g], 1.f);
    }
    __syncthreads();
    for (int idx = tid; idx < GG * 64; idx += 512) {
        int g = idx >> 6, j = idx & 63;
        float a = fc1b[j];
        for (int k = 0; k < HID; k++) a += pm[g * HID + k] * fc1w[k * 64 + j];
        z[idx] = a / (1.f + __expf(-a));
    }
    __syncthreads();
    int g = tid >> 5, lane = tid & 31;
    float s = z[g * 64 + lane] * fc2w[lane] + z[g * 64 + lane + 32] * fc2w[lane + 32];
#pragma unroll
    for (int o = 16; o; o >>= 1) s += __shfl_xor_sync(0xffffffffu, s, o);
    if (lane == 0) {
        float y = s + fc2b[0];
        out[g] = 1.f / (1.f + __expf(-y));
    }
}

// ---------------- launch ----------------------------------------------------
extern "C" void kernel_launch(void* const* d_in, const int* in_sizes, int n_in,
                              void* d_out, int out_size) {
    const float* x     = (const float*)d_in[0];
    const int*   ei    = (const int*)d_in[1];
    const int*   batch = (const int*)d_in[2];
    int p = 3;
    if (n_in > 3 && in_sizes[3] == 1) p = 4;   // num_graphs scalar present
    const float* W0      = (const float*)d_in[p + 0];
    const float* Ws      = (const float*)d_in[p + 1];
    const float* att_src = (const float*)d_in[p + 2];
    const float* att_dst = (const float*)d_in[p + 3];
    const float* bias    = (const float*)d_in[p + 4];
    const float* gamma   = (const float*)d_in[p + 5];
    const float* beta    = (const float*)d_in[p + 6];
    const float* fc1w    = (const float*)d_in[p + 7];
    const float* fc1b    = (const float*)d_in[p + 8];
    const float* fc2w    = (const float*)d_in[p + 9];
    const float* fc2b    = (const float*)d_in[p + 10];
    float* out = (float*)d_out;

    // CSR build (recomputed every call; deterministic work)
    k_zero_csr<<<(NN + 255) / 256, 256>>>();
    k_hist<<<(ETOT + 255) / 256, 256>>>(ei);
    k_scan_block<<<(NN + 1023) / 1024, 1024>>>();
    k_scan_sums<<<1, 32>>>();
    k_rowptr<<<(NN + 255) / 256, 256>>>();
    k_scatter<<<(ETOT + 255) / 256, 256>>>(ei);

    for (int l = 0; l < 4; l++) {
        if (l == 0) k_gemm0<<<(NN + 63) / 64, 128>>>(x, W0);
        else        k_gemm128<<<(NN + 63) / 64, 256>>>(Ws + (l - 1) * HID * HID);
        k_alpha<<<(NN + 1) / 2, 256>>>(att_src + l * HH * CC, att_dst + l * HH * CC);
        k_edge_e<<<(ETOT + 255) / 256, 256>>>();
        k_agg<<<(NN * HH + 7) / 8, 256>>>(bias + l * HID);
        k_bnzero<<<1, 128>>>();
        k_bnred<<<256, 256>>>();
        k_bnstats<<<1, 128>>>();
        k_bnapply<<<(NN * HID + 255) / 256, 256>>>(gamma + l * HID, beta + l * HID);
    }

    k_poolzero<<<(GG * HID + GG + 255) / 256, 256>>>();
    k_gcnt<<<(NN + 255) / 256, 256>>>(batch);
    k_pool<<<(NN + 255) / 256, 128>>>(batch);
    k_mlp<<<1, 512>>>(fc1w, fc1b, fc2w, fc2b, out);
}

// round 2
// speedup vs baseline: 1.0159x; 1.0159x over previous
#include <cuda_runtime.h>
#include <math.h>

#define NN   50000
#define EE   800000
#define ETOT (EE + NN)      // 850000 edges incl. self loops
#define HID  128
#define HH   4
#define CC   32
#define GG   16
#define NEG  0.2f
#define EPSV 1e-5f

// ---------------- scratch (device globals; no runtime allocation) ----------
__device__ float g_h0[NN * HID];        // GEMM output / message source
__device__ float g_h1[NN * HID];        // agg output (raw, pre-BN)
__device__ float g_as[NN * HH];
__device__ float g_ad[NN * HH];
__device__ int   g_cnt[NN];
__device__ int   g_cur[NN];
__device__ int   g_incl[NN];
__device__ int   g_rowptr[NN + 1];
__device__ int   g_col[ETOT];           // src per CSR slot
__device__ int   g_bsum[64];
__device__ float g_bnsum[HID], g_bnsq[HID];
__device__ float g_scale[HID], g_shift[HID];   // BN affine folded: y = v*scale+shift
__device__ float g_pool[GG * HID];
__device__ int   g_gcnt[GG];

__device__ __forceinline__ float silu_f(float y) { return y / (1.f + __expf(-y)); }

// ---------------- CSR build -------------------------------------------------
__global__ void k_zero_csr() {
    int i = blockIdx.x * blockDim.x + threadIdx.x;
    if (i < NN) { g_cnt[i] = 0; g_cur[i] = 0; }
}

__global__ void k_hist(const int* __restrict__ ei) {
    int e = blockIdx.x * blockDim.x + threadIdx.x;
    if (e >= ETOT) return;
    int d = (e < EE) ? ei[EE + e] : (e - EE);
    atomicAdd(&g_cnt[d], 1);
}

__global__ void k_scan_block() {
    __shared__ int s[1024];
    int i = blockIdx.x * 1024 + threadIdx.x;
    int v = (i < NN) ? g_cnt[i] : 0;
    s[threadIdx.x] = v;
    __syncthreads();
    for (int off = 1; off < 1024; off <<= 1) {
        int t = (threadIdx.x >= off) ? s[threadIdx.x - off] : 0;
        __syncthreads();
        s[threadIdx.x] += t;
        __syncthreads();
    }
    if (i < NN) g_incl[i] = s[threadIdx.x];
    if (threadIdx.x == 1023) g_bsum[blockIdx.x] = s[1023];
}

// exclusive scan of the 49 block sums with one 64-thread block
__global__ void k_scan_sums() {
    __shared__ int s[64];
    int t = threadIdx.x;
    const int nb = (NN + 1023) / 1024;
    int v = (t < nb) ? g_bsum[t] : 0;
    s[t] = v;
    __syncthreads();
    for (int off = 1; off < 64; off <<= 1) {
        int u = (t >= off) ? s[t - off] : 0;
        __syncthreads();
        s[t] += u;
        __syncthreads();
    }
    g_bsum[t] = s[t] - v;   // exclusive
}

__global__ void k_rowptr() {
    int i = blockIdx.x * blockDim.x + threadIdx.x;
    if (i < NN) g_rowptr[i] = g_incl[i] - g_cnt[i] + g_bsum[i >> 10];
    if (i == 0) g_rowptr[NN] = ETOT;
}

__global__ void k_scatter(const int* __restrict__ ei) {
    int e = blockIdx.x * blockDim.x + threadIdx.x;
    if (e >= ETOT) return;
    int s, d;
    if (e < EE) { s = ei[e]; d = ei[EE + e]; }
    else        { s = e - EE; d = s; }
    int pos = g_rowptr[d] + atomicAdd(&g_cur[d], 1);
    g_col[pos] = s;
}

// ---------------- GEMMs -----------------------------------------------------
// layer 0: [N,5] @ [5,128] -> g_h0  (raw x input)
__global__ void k_gemm0(const float* __restrict__ X, const float* __restrict__ W0) {
    __shared__ float w[5 * HID];
    int tid = threadIdx.x;   // 128
    for (int i = tid; i < 5 * HID; i += 128) w[i] = W0[i];
    __syncthreads();
    int r0 = blockIdx.x * 64;
    for (int rr = 0; rr < 64; rr++) {
        int r = r0 + rr;
        if (r >= NN) break;
        float a = 0.f;
#pragma unroll
        for (int k = 0; k < 5; k++) a += X[r * 5 + k] * w[k * HID + tid];
        g_h0[r * HID + tid] = a;
    }
}

// per (node, head) dot for layer 0 (layers 1-3 fuse this into the GEMM)
__global__ void k_alpha(const float* __restrict__ asrc, const float* __restrict__ adst) {
    int n = blockIdx.x * 2 + (threadIdx.x >> 7);
    if (n >= NN) return;
    int t = threadIdx.x & 127;
    int hh = t >> 5, lane = t & 31;
    float v  = g_h0[n * HID + t];
    float s1 = v * asrc[t];
    float s2 = v * adst[t];
#pragma unroll
    for (int o = 16; o; o >>= 1) {
        s1 += __shfl_xor_sync(0xffffffffu, s1, o);
        s2 += __shfl_xor_sync(0xffffffffu, s2, o);
    }
    if (lane == 0) { g_as[n * HH + hh] = s1; g_ad[n * HH + hh] = s2; }
}

// layers 1..3: h0 = silu(bn(g_h1)) @ B, fused alpha epilogue.
// tile 128x128, 256 threads, 8x8 microtile.
__global__ __launch_bounds__(256, 2) void k_gemm128(
    const float* __restrict__ B,
    const float* __restrict__ asrc, const float* __restrict__ adst)
{
    __shared__ float As[8][128];
    __shared__ float Bs[8][128];
    __shared__ float sc[HID], sh[HID];
    __shared__ float2 red[128][17];
    int tid = threadIdx.x;
    int tx = tid & 15, ty = tid >> 4;
    int row0 = blockIdx.x * 128;
    if (tid < HID) { sc[tid] = g_scale[tid]; sh[tid] = g_shift[tid]; }
    __syncthreads();

    float acc[8][8];
#pragma unroll
    for (int i = 0; i < 8; i++)
#pragma unroll
        for (int j = 0; j < 8; j++) acc[i][j] = 0.f;

    for (int k0 = 0; k0 < 128; k0 += 8) {
        // A tile: 128 rows x 8 k, BN+SiLU applied at load
        {
            int r = tid >> 1, kq = (tid & 1) * 4;
            int row = row0 + r;
            float4 v = (row < NN) ? *(const float4*)&g_h1[row * HID + k0 + kq]
                                  : make_float4(0.f, 0.f, 0.f, 0.f);
            float vv[4] = {v.x, v.y, v.z, v.w};
#pragma unroll
            for (int q = 0; q < 4; q++) {
                int k = kq + q;
                float y = vv[q] * sc[k0 + k] + sh[k0 + k];
                As[k][r] = silu_f(y);
            }
        }
        // B tile: 8 k x 128 cols, coalesced
        {
            int k = tid >> 5, c = (tid & 31) * 4;
            *(float4*)&Bs[k][c] = *(const float4*)&B[(k0 + k) * HID + c];
        }
        __syncthreads();
#pragma unroll
        for (int k = 0; k < 8; k++) {
            float av[8], bv[8];
            *(float4*)&av[0] = *(const float4*)&As[k][ty * 8];
            *(float4*)&av[4] = *(const float4*)&As[k][ty * 8 + 4];
            *(float4*)&bv[0] = *(const float4*)&Bs[k][tx * 8];
            *(float4*)&bv[4] = *(const float4*)&Bs[k][tx * 8 + 4];
#pragma unroll
            for (int i = 0; i < 8; i++)
#pragma unroll
                for (int j = 0; j < 8; j++) acc[i][j] += av[i] * bv[j];
        }
        __syncthreads();
    }

    // store + alpha partials (cols tx*8..+8 all belong to head tx>>2)
    float a_s[8], a_d[8];
    *(float4*)&a_s[0] = *(const float4*)&asrc[tx * 8];
    *(float4*)&a_s[4] = *(const float4*)&asrc[tx * 8 + 4];
    *(float4*)&a_d[0] = *(const float4*)&adst[tx * 8];
    *(float4*)&a_d[4] = *(const float4*)&adst[tx * 8 + 4];
#pragma unroll
    for (int i = 0; i < 8; i++) {
        int row = row0 + ty * 8 + i;
        float ps = 0.f, pd = 0.f;
#pragma unroll
        for (int j = 0; j < 8; j++) { ps += acc[i][j] * a_s[j]; pd += acc[i][j] * a_d[j]; }
        if (row < NN) {
            float4 v0 = make_float4(acc[i][0], acc[i][1], acc[i][2], acc[i][3]);
            float4 v1 = make_float4(acc[i][4], acc[i][5], acc[i][6], acc[i][7]);
            *(float4*)&g_h0[row * HID + tx * 8]     = v0;
            *(float4*)&g_h0[row * HID + tx * 8 + 4] = v1;
        }
        red[ty * 8 + i][tx] = make_float2(ps, pd);
    }
    __syncthreads();
    if (tid < 128) {
        int row = row0 + tid;
        if (row < NN) {
#pragma unroll
            for (int hh = 0; hh < HH; hh++) {
                float s1 = 0.f, s2 = 0.f;
#pragma unroll
                for (int q = 0; q < 4; q++) {
                    float2 p = red[tid][hh * 4 + q];
                    s1 += p.x; s2 += p.y;
                }
                g_as[row * HH + hh] = s1;
                g_ad[row * HH + hh] = s2;
            }
        }
    }
}

// ---------------- aggregation: online softmax + gather ----------------------
__global__ void k_agg(const float* __restrict__ bias_l) {
    int gw   = blockIdx.x * (blockDim.x >> 5) + (threadIdx.x >> 5);
    int lane = threadIdx.x & 31;
    if (gw >= NN * HH) return;
    int n = gw >> 2, hh = gw & 3;
    int beg = g_rowptr[n], end = g_rowptr[n + 1];
    float ad = g_ad[n * HH + hh];

    // online max + sum over this (node, head)'s edges, lane-parallel
    float m_l = -1e30f, s_l = 0.f;
    for (int i = beg + lane; i < end; i += 32) {
        float a = g_as[g_col[i] * HH + hh] + ad;
        float e = (a > 0.f) ? a : NEG * a;
        if (e > m_l) { s_l *= __expf(m_l - e); m_l = e; }
        s_l += __expf(e - m_l);
    }
    float m = m_l;
#pragma unroll
    for (int o = 16; o; o >>= 1) m = fmaxf(m, __shfl_xor_sync(0xffffffffu, m, o));
    float s = s_l * __expf(m_l - m);
#pragma unroll
    for (int o = 16; o; o >>= 1) s += __shfl_xor_sync(0xffffffffu, s, o);
    float inv = 1.f / (s + 1e-16f);

    // weighted gather, serial over edges, lane = channel
    float acc = 0.f;
    int hc = hh * CC + lane;
    for (int i = beg; i < end; i++) {
        int sn = g_col[i];                       // broadcast
        float a = g_as[sn * HH + hh] + ad;       // broadcast
        float e = (a > 0.f) ? a : NEG * a;
        acc += __expf(e - m) * g_h0[sn * HID + hc];  // coalesced 128B row
    }
    g_h1[n * HID + hc] = acc * inv + bias_l[hc];
}

// ---------------- batchnorm stats (apply is fused into consumers) -----------
__global__ void k_bnzero() {
    int t = threadIdx.x;
    if (t < HID) { g_bnsum[t] = 0.f; g_bnsq[t] = 0.f; }
}

__global__ void k_bnred() {
    __shared__ float ss[256], sq[256];
    int col = threadIdx.x & 127;
    int rp  = threadIdx.x >> 7;
    float s = 0.f, q = 0.f;
    for (int r = blockIdx.x * 2 + rp; r < NN; r += gridDim.x * 2) {
        float v = g_h1[r * HID + col];
        s += v; q += v * v;
    }
    ss[threadIdx.x] = s; sq[threadIdx.x] = q;
    __syncthreads();
    if (threadIdx.x < 128) {
        atomicAdd(&g_bnsum[col], ss[threadIdx.x] + ss[threadIdx.x + 128]);
        atomicAdd(&g_bnsq[col],  sq[threadIdx.x] + sq[threadIdx.x + 128]);
    }
}

__global__ void k_bnstats(const float* __restrict__ gamma, const float* __restrict__ beta) {
    int t = threadIdx.x;
    if (t < HID) {
        float mean = g_bnsum[t] / (float)NN;
        float var  = g_bnsq[t] / (float)NN - mean * mean;
        float rstd = rsqrtf(var + EPSV);
        float scl  = rstd * gamma[t];
        g_scale[t] = scl;
        g_shift[t] = beta[t] - mean * scl;
    }
}

// ---------------- pooling + MLP ---------------------------------------------
__global__ void k_poolzero() {
    int i = blockIdx.x * blockDim.x + threadIdx.x;
    if (i < GG * HID) g_pool[i] = 0.f;
    if (i >= GG * HID && i < GG * HID + GG) g_gcnt[i - GG * HID] = 0;
}

__global__ void k_gcnt(const int* __restrict__ batch) {
    __shared__ int sc[GG];
    if (threadIdx.x < GG) sc[threadIdx.x] = 0;
    __syncthreads();
    int i = blockIdx.x * blockDim.x + threadIdx.x;
    if (i < NN) atomicAdd(&sc[batch[i]], 1);
    __syncthreads();
    if (threadIdx.x < GG && sc[threadIdx.x]) atomicAdd(&g_gcnt[threadIdx.x], sc[threadIdx.x]);
}

// batch sorted -> running accumulator; BN+SiLU of layer 3 fused into the load
__global__ void k_pool(const int* __restrict__ batch) {
    int col = threadIdx.x;     // 128
    int r0  = blockIdx.x * 256;
    if (r0 >= NN) return;
    float scl = g_scale[col], shf = g_shift[col];
    int rend = min(r0 + 256, NN);
    int cur  = batch[r0];
    float acc = 0.f;
    for (int r = r0; r < rend; r++) {
        int g = batch[r];
        if (g != cur) { atomicAdd(&g_pool[cur * HID + col], acc); acc = 0.f; cur = g; }
        float y = g_h1[r * HID + col] * scl + shf;
        acc += silu_f(y);
    }
    atomicAdd(&g_pool[cur * HID + col], acc);
}

__global__ void k_mlp(const float* __restrict__ fc1w, const float* __restrict__ fc1b,
                      const float* __restrict__ fc2w, const float* __restrict__ fc2b,
                      float* __restrict__ out) {
    __shared__ float pm[GG * HID];
    __shared__ float z[GG * 64];
    int tid = threadIdx.x;   // 512
    for (int i = tid; i < GG * HID; i += 512) {
        int g = i >> 7;
        pm[i] = g_pool[i] / fmaxf((float)g_gcnt[g], 1.f);
    }
    __syncthreads();
    for (int idx = tid; idx < GG * 64; idx += 512) {
        int g = idx >> 6, j = idx & 63;
        float a = fc1b[j];
        for (int k = 0; k < HID; k++) a += pm[g * HID + k] * fc1w[k * 64 + j];
        z[idx] = silu_f(a);
    }
    __syncthreads();
    int g = tid >> 5, lane = tid & 31;
    if (g < GG) {
        float s = z[g * 64 + lane] * fc2w[lane] + z[g * 64 + lane + 32] * fc2w[lane + 32];
#pragma unroll
        for (int o = 16; o; o >>= 1) s += __shfl_xor_sync(0xffffffffu, s, o);
        if (lane == 0) {
            float y = s + fc2b[0];
            out[g] = 1.f / (1.f + __expf(-y));
        }
    }
}

// ---------------- launch ----------------------------------------------------
extern "C" void kernel_launch(void* const* d_in, const int* in_sizes, int n_in,
                              void* d_out, int out_size) {
    const float* x     = (const float*)d_in[0];
    const int*   ei    = (const int*)d_in[1];
    const int*   batch = (const int*)d_in[2];
    int p = 3;
    if (n_in > 3 && in_sizes[3] == 1) p = 4;   // num_graphs scalar present
    const float* W0      = (const float*)d_in[p + 0];
    const float* Ws      = (const float*)d_in[p + 1];
    const float* att_src = (const float*)d_in[p + 2];
    const float* att_dst = (const float*)d_in[p + 3];
    const float* bias    = (const float*)d_in[p + 4];
    const float* gamma   = (const float*)d_in[p + 5];
    const float* beta    = (const float*)d_in[p + 6];
    const float* fc1w    = (const float*)d_in[p + 7];
    const float* fc1b    = (const float*)d_in[p + 8];
    const float* fc2w    = (const float*)d_in[p + 9];
    const float* fc2b    = (const float*)d_in[p + 10];
    float* out = (float*)d_out;

    // CSR build
    k_zero_csr<<<(NN + 255) / 256, 256>>>();
    k_hist<<<(ETOT + 255) / 256, 256>>>(ei);
    k_scan_block<<<(NN + 1023) / 1024, 1024>>>();
    k_scan_sums<<<1, 64>>>();
    k_rowptr<<<(NN + 255) / 256, 256>>>();
    k_scatter<<<(ETOT + 255) / 256, 256>>>(ei);

    for (int l = 0; l < 4; l++) {
        if (l == 0) {
            k_gemm0<<<(NN + 63) / 64, 128>>>(x, W0);
            k_alpha<<<(NN + 1) / 2, 256>>>(att_src, att_dst);
        } else {
            k_gemm128<<<(NN + 127) / 128, 256>>>(Ws + (l - 1) * HID * HID,
                                                 att_src + l * HH * CC,
                                                 att_dst + l * HH * CC);
        }
        k_agg<<<(NN * HH + 7) / 8, 256>>>(bias + l * HID);
        k_bnzero<<<1, 128>>>();
        k_bnred<<<256, 256>>>();
        k_bnstats<<<1, 128>>>(gamma + l * HID, beta + l * HID);
    }

    k_poolzero<<<(GG * HID + GG + 255) / 256, 256>>>();
    k_gcnt<<<(NN + 255) / 256, 256>>>(batch);
    k_pool<<<(NN + 255) / 256, 128>>>(batch);
    k_mlp<<<1, 512>>>(fc1w, fc1b, fc2w, fc2b, out);
}

// round 3
// speedup vs baseline: 1.1388x; 1.1210x over previous
#include <cuda_runtime.h>
#include <math.h>

#define NN   50000
#define EE   800000
#define ETOT (EE + NN)      // 850000 edges incl. self loops
#define HID  128
#define HH   4
#define CC   32
#define GG   16
#define NEG  0.2f
#define EPSV 1e-5f
#define NBNB 256            // bn reduction blocks

// ---------------- scratch (device globals; no runtime allocation) ----------
__device__ float g_h0[NN * HID];        // GEMM output / message source
__device__ float g_h1[NN * HID];        // agg output (raw, pre-BN)
__device__ float g_as[NN * HH];
__device__ float g_ad[NN * HH];
__device__ int   g_cnt[NN];
__device__ int   g_cur[NN];
__device__ int   g_incl[NN];
__device__ int   g_rowptr[NN + 1];
__device__ int   g_col[ETOT];           // src per CSR slot
__device__ int   g_bsum[64];
__device__ float g_psum[NBNB * HID], g_psq[NBNB * HID];
__device__ float g_scale[HID], g_shift[HID];   // BN affine folded: y = v*scale+shift
__device__ float g_pool[GG * HID];
__device__ int   g_gcnt[GG];

__device__ __forceinline__ float silu_f(float y) { return y / (1.f + __expf(-y)); }
__device__ __forceinline__ float lrelu_f(float a) { return (a > 0.f) ? a : NEG * a; }

// ---------------- CSR build -------------------------------------------------
__global__ void k_zero_csr() {
    int i = blockIdx.x * blockDim.x + threadIdx.x;
    if (i < NN) { g_cnt[i] = 0; g_cur[i] = 0; }
}

__global__ void k_hist(const int* __restrict__ ei) {
    int e = blockIdx.x * blockDim.x + threadIdx.x;
    if (e >= ETOT) return;
    int d = (e < EE) ? ei[EE + e] : (e - EE);
    atomicAdd(&g_cnt[d], 1);
}

__global__ void k_scan_block() {
    __shared__ int s[1024];
    int i = blockIdx.x * 1024 + threadIdx.x;
    int v = (i < NN) ? g_cnt[i] : 0;
    s[threadIdx.x] = v;
    __syncthreads();
    for (int off = 1; off < 1024; off <<= 1) {
        int t = (threadIdx.x >= off) ? s[threadIdx.x - off] : 0;
        __syncthreads();
        s[threadIdx.x] += t;
        __syncthreads();
    }
    if (i < NN) g_incl[i] = s[threadIdx.x];
    if (threadIdx.x == 1023) g_bsum[blockIdx.x] = s[1023];
}

__global__ void k_scan_sums() {
    __shared__ int s[64];
    int t = threadIdx.x;
    const int nb = (NN + 1023) / 1024;
    int v = (t < nb) ? g_bsum[t] : 0;
    s[t] = v;
    __syncthreads();
    for (int off = 1; off < 64; off <<= 1) {
        int u = (t >= off) ? s[t - off] : 0;
        __syncthreads();
        s[t] += u;
        __syncthreads();
    }
    g_bsum[t] = s[t] - v;   // exclusive
}

__global__ void k_rowptr() {
    int i = blockIdx.x * blockDim.x + threadIdx.x;
    if (i < NN) g_rowptr[i] = g_incl[i] - g_cnt[i] + g_bsum[i >> 10];
    if (i == 0) g_rowptr[NN] = ETOT;
}

__global__ void k_scatter(const int* __restrict__ ei) {
    int e = blockIdx.x * blockDim.x + threadIdx.x;
    if (e >= ETOT) return;
    int s, d;
    if (e < EE) { s = ei[e]; d = ei[EE + e]; }
    else        { s = e - EE; d = s; }
    int pos = g_rowptr[d] + atomicAdd(&g_cur[d], 1);
    g_col[pos] = s;
}

// ---------------- GEMMs -----------------------------------------------------
// layer 0: [N,5] @ [5,128] -> g_h0  (raw x input)
__global__ void k_gemm0(const float* __restrict__ X, const float* __restrict__ W0) {
    __shared__ float w[5 * HID];
    __shared__ float xs[64 * 5];
    int tid = threadIdx.x;   // 128
    for (int i = tid; i < 5 * HID; i += 128) w[i] = W0[i];
    int r0 = blockIdx.x * 64;
    int nr = min(64, NN - r0);
    for (int i = tid; i < nr * 5; i += 128) xs[i] = X[r0 * 5 + i];
    __syncthreads();
    for (int rr = 0; rr < nr; rr++) {
        float a = 0.f;
#pragma unroll
        for (int k = 0; k < 5; k++) a += xs[rr * 5 + k] * w[k * HID + tid];
        g_h0[(r0 + rr) * HID + tid] = a;
    }
}

// per (node, head) dot for layer 0 (layers 1-3 fuse this into the GEMM)
__global__ void k_alpha(const float* __restrict__ asrc, const float* __restrict__ adst) {
    int n = blockIdx.x * 2 + (threadIdx.x >> 7);
    if (n >= NN) return;
    int t = threadIdx.x & 127;
    int hh = t >> 5, lane = t & 31;
    float v  = g_h0[n * HID + t];
    float s1 = v * asrc[t];
    float s2 = v * adst[t];
#pragma unroll
    for (int o = 16; o; o >>= 1) {
        s1 += __shfl_xor_sync(0xffffffffu, s1, o);
        s2 += __shfl_xor_sync(0xffffffffu, s2, o);
    }
    if (lane == 0) { g_as[n * HH + hh] = s1; g_ad[n * HH + hh] = s2; }
}

// layers 1..3: h0 = silu(bn(g_h1)) @ B, fused alpha epilogue.
// tile 128x128, 256 threads, 8x8 microtile, register double-buffered.
__global__ __launch_bounds__(256, 2) void k_gemm128(
    const float* __restrict__ B,
    const float* __restrict__ asrc, const float* __restrict__ adst)
{
    __shared__ float As[8][128];
    __shared__ float Bs[8][128];
    __shared__ float sc[HID], sh[HID];
    __shared__ float2 red[128][17];
    int tid = threadIdx.x;
    int tx = tid & 15, ty = tid >> 4;
    int row0 = blockIdx.x * 128;
    if (tid < HID) { sc[tid] = g_scale[tid]; sh[tid] = g_shift[tid]; }

    // A-load mapping: r = tid>>1, kq = (tid&1)*4
    int ar = tid >> 1, akq = (tid & 1) * 4;
    int arow = row0 + ar;
    // B-load mapping
    int bk = tid >> 5, bc = (tid & 31) * 4;
    __syncthreads();

    float acc[8][8];
#pragma unroll
    for (int i = 0; i < 8; i++)
#pragma unroll
        for (int j = 0; j < 8; j++) acc[i][j] = 0.f;

    // prologue: tile 0
    float4 va = (arow < NN) ? *(const float4*)&g_h1[arow * HID + akq]
                            : make_float4(0.f, 0.f, 0.f, 0.f);
    float4 vb = *(const float4*)&B[bk * HID + bc];
    {
        float vv[4] = {va.x, va.y, va.z, va.w};
#pragma unroll
        for (int q = 0; q < 4; q++)
            As[akq + q][ar] = silu_f(vv[q] * sc[akq + q] + sh[akq + q]);
        *(float4*)&Bs[bk][bc] = vb;
    }
    __syncthreads();

    for (int k0 = 0; k0 < 128; k0 += 8) {
        // prefetch next tile into registers
        if (k0 + 8 < 128) {
            va = (arow < NN) ? *(const float4*)&g_h1[arow * HID + k0 + 8 + akq]
                             : make_float4(0.f, 0.f, 0.f, 0.f);
            vb = *(const float4*)&B[(k0 + 8 + bk) * HID + bc];
        }
#pragma unroll
        for (int k = 0; k < 8; k++) {
            float av[8], bv[8];
            *(float4*)&av[0] = *(const float4*)&As[k][ty * 8];
            *(float4*)&av[4] = *(const float4*)&As[k][ty * 8 + 4];
            *(float4*)&bv[0] = *(const float4*)&Bs[k][tx * 8];
            *(float4*)&bv[4] = *(const float4*)&Bs[k][tx * 8 + 4];
#pragma unroll
            for (int i = 0; i < 8; i++)
#pragma unroll
                for (int j = 0; j < 8; j++) acc[i][j] += av[i] * bv[j];
        }
        __syncthreads();
        if (k0 + 8 < 128) {
            float vv[4] = {va.x, va.y, va.z, va.w};
#pragma unroll
            for (int q = 0; q < 4; q++) {
                int k = k0 + 8 + akq + q;
                As[akq + q][ar] = silu_f(vv[q] * sc[k] + sh[k]);
            }
            *(float4*)&Bs[bk][bc] = vb;
            __syncthreads();
        }
    }

    // store + alpha partials (cols tx*8..+8 all belong to head tx>>2)
    float a_s[8], a_d[8];
    *(float4*)&a_s[0] = *(const float4*)&asrc[tx * 8];
    *(float4*)&a_s[4] = *(const float4*)&asrc[tx * 8 + 4];
    *(float4*)&a_d[0] = *(const float4*)&adst[tx * 8];
    *(float4*)&a_d[4] = *(const float4*)&adst[tx * 8 + 4];
#pragma unroll
    for (int i = 0; i < 8; i++) {
        int row = row0 + ty * 8 + i;
        float ps = 0.f, pd = 0.f;
#pragma unroll
        for (int j = 0; j < 8; j++) { ps += acc[i][j] * a_s[j]; pd += acc[i][j] * a_d[j]; }
        if (row < NN) {
            float4 v0 = make_float4(acc[i][0], acc[i][1], acc[i][2], acc[i][3]);
            float4 v1 = make_float4(acc[i][4], acc[i][5], acc[i][6], acc[i][7]);
            *(float4*)&g_h0[row * HID + tx * 8]     = v0;
            *(float4*)&g_h0[row * HID + tx * 8 + 4] = v1;
        }
        red[ty * 8 + i][tx] = make_float2(ps, pd);
    }
    __syncthreads();
    if (tid < 128) {
        int row = row0 + tid;
        if (row < NN) {
#pragma unroll
            for (int hh = 0; hh < HH; hh++) {
                float s1 = 0.f, s2 = 0.f;
#pragma unroll
                for (int q = 0; q < 4; q++) {
                    float2 p = red[tid][hh * 4 + q];
                    s1 += p.x; s2 += p.y;
                }
                g_as[row * HH + hh] = s1;
                g_ad[row * HH + hh] = s2;
            }
        }
    }
}

// ---------------- aggregation: online softmax + unrolled gather -------------
__global__ void k_agg(const float* __restrict__ bias_l) {
    int gw   = blockIdx.x * (blockDim.x >> 5) + (threadIdx.x >> 5);
    int lane = threadIdx.x & 31;
    if (gw >= NN * HH) return;
    int n = gw >> 2, hh = gw & 3;
    int beg = g_rowptr[n], end = g_rowptr[n + 1];
    float ad = g_ad[n * HH + hh];

    // pass 1: online max + sum, lane-parallel
    float m_l = -1e30f, s_l = 0.f;
    for (int i = beg + lane; i < end; i += 32) {
        float e = lrelu_f(g_as[g_col[i] * HH + hh] + ad);
        if (e > m_l) { s_l *= __expf(m_l - e); m_l = e; }
        s_l += __expf(e - m_l);
    }
    float m = m_l;
#pragma unroll
    for (int o = 16; o; o >>= 1) m = fmaxf(m, __shfl_xor_sync(0xffffffffu, m, o));
    float s = s_l * __expf(m_l - m);
#pragma unroll
    for (int o = 16; o; o >>= 1) s += __shfl_xor_sync(0xffffffffu, s, o);
    float inv = 1.f / (s + 1e-16f);

    // pass 2: weighted gather, unrolled x4 for MLP (accumulation order preserved)
    float acc = 0.f;
    int hc = hh * CC + lane;
    int i = beg;
    for (; i + 4 <= end; i += 4) {
        int s0 = g_col[i], s1 = g_col[i + 1], s2 = g_col[i + 2], s3 = g_col[i + 3];
        float w0 = __expf(lrelu_f(g_as[s0 * HH + hh] + ad) - m);
        float w1 = __expf(lrelu_f(g_as[s1 * HH + hh] + ad) - m);
        float w2 = __expf(lrelu_f(g_as[s2 * HH + hh] + ad) - m);
        float w3 = __expf(lrelu_f(g_as[s3 * HH + hh] + ad) - m);
        float h0v = g_h0[s0 * HID + hc];
        float h1v = g_h0[s1 * HID + hc];
        float h2v = g_h0[s2 * HID + hc];
        float h3v = g_h0[s3 * HID + hc];
        acc += w0 * h0v;
        acc += w1 * h1v;
        acc += w2 * h2v;
        acc += w3 * h3v;
    }
    for (; i < end; i++) {
        int sn = g_col[i];
        float w = __expf(lrelu_f(g_as[sn * HH + hh] + ad) - m);
        acc += w * g_h0[sn * HID + hc];
    }
    g_h1[n * HID + hc] = acc * inv + bias_l[hc];
}

// ---------------- batchnorm stats (apply is fused into consumers) -----------
__global__ void k_bnred() {
    __shared__ float ss[256], sq[256];
    int col = threadIdx.x & 127;
    int rp  = threadIdx.x >> 7;
    float s = 0.f, q = 0.f;
    for (int r = blockIdx.x * 2 + rp; r < NN; r += NBNB * 2) {
        float v = g_h1[r * HID + col];
        s += v; q += v * v;
    }
    ss[threadIdx.x] = s; sq[threadIdx.x] = q;
    __syncthreads();
    if (threadIdx.x < 128) {
        g_psum[blockIdx.x * HID + col] = ss[threadIdx.x] + ss[threadIdx.x + 128];
        g_psq[blockIdx.x * HID + col]  = sq[threadIdx.x] + sq[threadIdx.x + 128];
    }
}

__global__ void k_bnstats(const float* __restrict__ gamma, const float* __restrict__ beta) {
    int t = threadIdx.x;   // 128
    float s = 0.f, q = 0.f;
    for (int b = 0; b < NBNB; b++) {
        s += g_psum[b * HID + t];
        q += g_psq[b * HID + t];
    }
    float mean = s / (float)NN;
    float var  = q / (float)NN - mean * mean;
    float rstd = rsqrtf(var + EPSV);
    float scl  = rstd * gamma[t];
    g_scale[t] = scl;
    g_shift[t] = beta[t] - mean * scl;
}

// ---------------- pooling + MLP ---------------------------------------------
__global__ void k_poolzero() {
    int i = blockIdx.x * blockDim.x + threadIdx.x;
    if (i < GG * HID) g_pool[i] = 0.f;
    if (i >= GG * HID && i < GG * HID + GG) g_gcnt[i - GG * HID] = 0;
}

__global__ void k_gcnt(const int* __restrict__ batch) {
    __shared__ int sc[GG];
    if (threadIdx.x < GG) sc[threadIdx.x] = 0;
    __syncthreads();
    int i = blockIdx.x * blockDim.x + threadIdx.x;
    if (i < NN) atomicAdd(&sc[batch[i]], 1);
    __syncthreads();
    if (threadIdx.x < GG && sc[threadIdx.x]) atomicAdd(&g_gcnt[threadIdx.x], sc[threadIdx.x]);
}

// batch sorted -> running accumulator; BN+SiLU of layer 3 fused into the load
__global__ void k_pool(const int* __restrict__ batch) {
    int col = threadIdx.x;     // 128
    int r0  = blockIdx.x * 256;
    if (r0 >= NN) return;
    float scl = g_scale[col], shf = g_shift[col];
    int rend = min(r0 + 256, NN);
    int cur  = batch[r0];
    float acc = 0.f;
    for (int r = r0; r < rend; r++) {
        int g = batch[r];
        if (g != cur) { atomicAdd(&g_pool[cur * HID + col], acc); acc = 0.f; cur = g; }
        float y = g_h1[r * HID + col] * scl + shf;
        acc += silu_f(y);
    }
    atomicAdd(&g_pool[cur * HID + col], acc);
}

__global__ void k_mlp(const float* __restrict__ fc1w, const float* __restrict__ fc1b,
                      const float* __restrict__ fc2w, const float* __restrict__ fc2b,
                      float* __restrict__ out) {
    __shared__ float pm[GG * HID];
    __shared__ float z[GG * 64];
    int tid = threadIdx.x;   // 512
    for (int i = tid; i < GG * HID; i += 512) {
        int g = i >> 7;
        pm[i] = g_pool[i] / fmaxf((float)g_gcnt[g], 1.f);
    }
    __syncthreads();
    for (int idx = tid; idx < GG * 64; idx += 512) {
        int g = idx >> 6, j = idx & 63;
        float a = fc1b[j];
        for (int k = 0; k < HID; k++) a += pm[g * HID + k] * fc1w[k * 64 + j];
        z[idx] = silu_f(a);
    }
    __syncthreads();
    int g = tid >> 5, lane = tid & 31;
    if (g < GG) {
        float s = z[g * 64 + lane] * fc2w[lane] + z[g * 64 + lane + 32] * fc2w[lane + 32];
#pragma unroll
        for (int o = 16; o; o >>= 1) s += __shfl_xor_sync(0xffffffffu, s, o);
        if (lane == 0) {
            float y = s + fc2b[0];
            out[g] = 1.f / (1.f + __expf(-y));
        }
    }
}

// ---------------- launch ----------------------------------------------------
extern "C" void kernel_launch(void* const* d_in, const int* in_sizes, int n_in,
                              void* d_out, int out_size) {
    const float* x     = (const float*)d_in[0];
    const int*   ei    = (const int*)d_in[1];
    const int*   batch = (const int*)d_in[2];
    int p = 3;
    if (n_in > 3 && in_sizes[3] == 1) p = 4;   // num_graphs scalar present
    const float* W0      = (const float*)d_in[p + 0];
    const float* Ws      = (const float*)d_in[p + 1];
    const float* att_src = (const float*)d_in[p + 2];
    const float* att_dst = (const float*)d_in[p + 3];
    const float* bias    = (const float*)d_in[p + 4];
    const float* gamma   = (const float*)d_in[p + 5];
    const float* beta    = (const float*)d_in[p + 6];
    const float* fc1w    = (const float*)d_in[p + 7];
    const float* fc1b    = (const float*)d_in[p + 8];
    const float* fc2w    = (const float*)d_in[p + 9];
    const float* fc2b    = (const float*)d_in[p + 10];
    float* out = (float*)d_out;

    // CSR build
    k_zero_csr<<<(NN + 255) / 256, 256>>>();
    k_hist<<<(ETOT + 255) / 256, 256>>>(ei);
    k_scan_block<<<(NN + 1023) / 1024, 1024>>>();
    k_scan_sums<<<1, 64>>>();
    k_rowptr<<<(NN + 255) / 256, 256>>>();
    k_scatter<<<(ETOT + 255) / 256, 256>>>(ei);

    for (int l = 0; l < 4; l++) {
        if (l == 0) {
            k_gemm0<<<(NN + 63) / 64, 128>>>(x, W0);
            k_alpha<<<(NN + 1) / 2, 256>>>(att_src, att_dst);
        } else {
            k_gemm128<<<(NN + 127) / 128, 256>>>(Ws + (l - 1) * HID * HID,
                                                 att_src + l * HH * CC,
                                                 att_dst + l * HH * CC);
        }
        k_agg<<<(NN * HH + 7) / 8, 256>>>(bias + l * HID);
        k_bnred<<<NBNB, 256>>>();
        k_bnstats<<<1, 128>>>(gamma + l * HID, beta + l * HID);
    }

    k_poolzero<<<(GG * HID + GG + 255) / 256, 256>>>();
    k_gcnt<<<(NN + 255) / 256, 256>>>(batch);
    k_pool<<<(NN + 255) / 256, 128>>>(batch);
    k_mlp<<<1, 512>>>(fc1w, fc1b, fc2w, fc2b, out);
}

// round 4
// speedup vs baseline: 1.2186x; 1.0701x over previous
#include <cuda_runtime.h>
#include <math.h>

#define NN   50000
#define EE   800000
#define ETOT (EE + NN)      // 850000 edges incl. self loops
#define HID  128
#define HH   4
#define CC   32
#define GG   16
#define NEG  0.2f
#define EPSV 1e-5f
#define NBNB 256            // bn reduction blocks
#define ECHUNK 128

// ---------------- scratch ----------------------------------------------------
__device__ float g_h0[NN * HID];        // GEMM output / message source
__device__ float g_h1[NN * HID];        // agg output (raw, pre-BN)
__device__ float g_as[NN * HH];         // [n*4+h], float4-aligned
__device__ float g_ad[NN * HH];
__device__ int   g_cnt[NN];
__device__ int   g_cur[NN];
__device__ int   g_incl[NN];
__device__ int   g_rowptr[NN + 1];
__device__ int   g_col[ETOT];
__device__ int   g_bsum[64];
__device__ float g_psum[NBNB * HID], g_psq[NBNB * HID];
__device__ float g_scale[HID], g_shift[HID];
__device__ float g_pool[GG * HID];
__device__ int   g_gcnt[GG];

__device__ __forceinline__ float silu_f(float y) { return y / (1.f + __expf(-y)); }
__device__ __forceinline__ float lrelu_f(float a) { return (a > 0.f) ? a : NEG * a; }

// ---------------- CSR build -------------------------------------------------
__global__ void k_zero_csr() {
    int i = blockIdx.x * blockDim.x + threadIdx.x;
    if (i < NN) { g_cnt[i] = 0; g_cur[i] = 0; }
}

__global__ void k_hist(const int* __restrict__ ei) {
    int e = blockIdx.x * blockDim.x + threadIdx.x;
    if (e >= ETOT) return;
    int d = (e < EE) ? ei[EE + e] : (e - EE);
    atomicAdd(&g_cnt[d], 1);
}

__global__ void k_scan_block() {
    __shared__ int s[1024];
    int i = blockIdx.x * 1024 + threadIdx.x;
    int v = (i < NN) ? g_cnt[i] : 0;
    s[threadIdx.x] = v;
    __syncthreads();
    for (int off = 1; off < 1024; off <<= 1) {
        int t = (threadIdx.x >= off) ? s[threadIdx.x - off] : 0;
        __syncthreads();
        s[threadIdx.x] += t;
        __syncthreads();
    }
    if (i < NN) g_incl[i] = s[threadIdx.x];
    if (threadIdx.x == 1023) g_bsum[blockIdx.x] = s[1023];
}

__global__ void k_scan_sums() {
    __shared__ int s[64];
    int t = threadIdx.x;
    const int nb = (NN + 1023) / 1024;
    int v = (t < nb) ? g_bsum[t] : 0;
    s[t] = v;
    __syncthreads();
    for (int off = 1; off < 64; off <<= 1) {
        int u = (t >= off) ? s[t - off] : 0;
        __syncthreads();
        s[t] += u;
        __syncthreads();
    }
    g_bsum[t] = s[t] - v;   // exclusive
}

__global__ void k_rowptr() {
    int i = blockIdx.x * blockDim.x + threadIdx.x;
    if (i < NN) g_rowptr[i] = g_incl[i] - g_cnt[i] + g_bsum[i >> 10];
    if (i == 0) g_rowptr[NN] = ETOT;
}

__global__ void k_scatter(const int* __restrict__ ei) {
    int e = blockIdx.x * blockDim.x + threadIdx.x;
    if (e >= ETOT) return;
    int s, d;
    if (e < EE) { s = ei[e]; d = ei[EE + e]; }
    else        { s = e - EE; d = s; }
    int pos = g_rowptr[d] + atomicAdd(&g_cur[d], 1);
    g_col[pos] = s;
}

// ---------------- layer-0 GEMM with fused alpha ------------------------------
__global__ void k_gemm0(const float* __restrict__ X, const float* __restrict__ W0,
                        const float* __restrict__ asrc, const float* __restrict__ adst) {
    __shared__ float w[5 * HID];
    __shared__ float xs[64 * 5];
    int tid = threadIdx.x;   // 128
    int hh = tid >> 5, lane = tid & 31;
    for (int i = tid; i < 5 * HID; i += 128) w[i] = W0[i];
    int r0 = blockIdx.x * 64;
    int nr = min(64, NN - r0);
    for (int i = tid; i < nr * 5; i += 128) xs[i] = X[r0 * 5 + i];
    __syncthreads();
    float avs = asrc[tid], avd = adst[tid];
    for (int rr = 0; rr < nr; rr++) {
        float a = 0.f;
#pragma unroll
        for (int k = 0; k < 5; k++) a += xs[rr * 5 + k] * w[k * HID + tid];
        g_h0[(r0 + rr) * HID + tid] = a;
        float s1 = a * avs, s2 = a * avd;
#pragma unroll
        for (int o = 16; o; o >>= 1) {
            s1 += __shfl_xor_sync(0xffffffffu, s1, o);
            s2 += __shfl_xor_sync(0xffffffffu, s2, o);
        }
        if (lane == 0) {
            g_as[(r0 + rr) * HH + hh] = s1;
            g_ad[(r0 + rr) * HH + hh] = s2;
        }
    }
}

// ---------------- layers 1..3 GEMM (BN+SiLU on load, alpha epilogue) ---------
__global__ __launch_bounds__(256, 2) void k_gemm128(
    const float* __restrict__ B,
    const float* __restrict__ asrc, const float* __restrict__ adst)
{
    __shared__ float As[8][128];
    __shared__ float Bs[8][128];
    __shared__ float sc[HID], sh[HID];
    __shared__ float2 red[128][17];
    int tid = threadIdx.x;
    int tx = tid & 15, ty = tid >> 4;
    int row0 = blockIdx.x * 128;
    if (tid < HID) { sc[tid] = g_scale[tid]; sh[tid] = g_shift[tid]; }

    int ar = tid >> 1, akq = (tid & 1) * 4;
    int arow = row0 + ar;
    int bk = tid >> 5, bc = (tid & 31) * 4;
    __syncthreads();

    float acc[8][8];
#pragma unroll
    for (int i = 0; i < 8; i++)
#pragma unroll
        for (int j = 0; j < 8; j++) acc[i][j] = 0.f;

    float4 va = (arow < NN) ? *(const float4*)&g_h1[arow * HID + akq]
                            : make_float4(0.f, 0.f, 0.f, 0.f);
    float4 vb = *(const float4*)&B[bk * HID + bc];
    {
        float vv[4] = {va.x, va.y, va.z, va.w};
#pragma unroll
        for (int q = 0; q < 4; q++)
            As[akq + q][ar] = silu_f(vv[q] * sc[akq + q] + sh[akq + q]);
        *(float4*)&Bs[bk][bc] = vb;
    }
    __syncthreads();

    for (int k0 = 0; k0 < 128; k0 += 8) {
        if (k0 + 8 < 128) {
            va = (arow < NN) ? *(const float4*)&g_h1[arow * HID + k0 + 8 + akq]
                             : make_float4(0.f, 0.f, 0.f, 0.f);
            vb = *(const float4*)&B[(k0 + 8 + bk) * HID + bc];
        }
#pragma unroll
        for (int k = 0; k < 8; k++) {
            float av[8], bv[8];
            *(float4*)&av[0] = *(const float4*)&As[k][ty * 8];
            *(float4*)&av[4] = *(const float4*)&As[k][ty * 8 + 4];
            *(float4*)&bv[0] = *(const float4*)&Bs[k][tx * 8];
            *(float4*)&bv[4] = *(const float4*)&Bs[k][tx * 8 + 4];
#pragma unroll
            for (int i = 0; i < 8; i++)
#pragma unroll
                for (int j = 0; j < 8; j++) acc[i][j] += av[i] * bv[j];
        }
        __syncthreads();
        if (k0 + 8 < 128) {
            float vv[4] = {va.x, va.y, va.z, va.w};
#pragma unroll
            for (int q = 0; q < 4; q++) {
                int k = k0 + 8 + akq + q;
                As[akq + q][ar] = silu_f(vv[q] * sc[k] + sh[k]);
            }
            *(float4*)&Bs[bk][bc] = vb;
            __syncthreads();
        }
    }

    float a_s[8], a_d[8];
    *(float4*)&a_s[0] = *(const float4*)&asrc[tx * 8];
    *(float4*)&a_s[4] = *(const float4*)&asrc[tx * 8 + 4];
    *(float4*)&a_d[0] = *(const float4*)&adst[tx * 8];
    *(float4*)&a_d[4] = *(const float4*)&adst[tx * 8 + 4];
#pragma unroll
    for (int i = 0; i < 8; i++) {
        int row = row0 + ty * 8 + i;
        float ps = 0.f, pd = 0.f;
#pragma unroll
        for (int j = 0; j < 8; j++) { ps += acc[i][j] * a_s[j]; pd += acc[i][j] * a_d[j]; }
        if (row < NN) {
            float4 v0 = make_float4(acc[i][0], acc[i][1], acc[i][2], acc[i][3]);
            float4 v1 = make_float4(acc[i][4], acc[i][5], acc[i][6], acc[i][7]);
            *(float4*)&g_h0[row * HID + tx * 8]     = v0;
            *(float4*)&g_h0[row * HID + tx * 8 + 4] = v1;
        }
        red[ty * 8 + i][tx] = make_float2(ps, pd);
    }
    __syncthreads();
    if (tid < 128) {
        int row = row0 + tid;
        if (row < NN) {
#pragma unroll
            for (int hh = 0; hh < HH; hh++) {
                float s1 = 0.f, s2 = 0.f;
#pragma unroll
                for (int q = 0; q < 4; q++) {
                    float2 p = red[tid][hh * 4 + q];
                    s1 += p.x; s2 += p.y;
                }
                g_as[row * HH + hh] = s1;
                g_ad[row * HH + hh] = s2;
            }
        }
    }
}

// ---------------- aggregation: block-per-node, SMEM-staged weights ----------
__global__ __launch_bounds__(128, 8) void k_agg(const float* __restrict__ bias_l) {
    __shared__ int   s_col[ECHUNK];
    __shared__ float s_e[HH][ECHUNK];
    int n = blockIdx.x;
    int tid = threadIdx.x;            // 128
    int hh = tid >> 5, lane = tid & 31;
    int beg = g_rowptr[n], end = g_rowptr[n + 1];
    float4 ad4 = *(const float4*)&g_ad[n * HH];

    float m_run = -1e30f, s_run = 0.f, acc = 0.f;

    for (int c0 = beg; c0 < end; c0 += ECHUNK) {
        int cnt = min(ECHUNK, end - c0);
        __syncthreads();
        if (tid < cnt) {
            int s = g_col[c0 + tid];
            s_col[tid] = s;
            float4 av = *(const float4*)&g_as[s * HH];
            s_e[0][tid] = lrelu_f(av.x + ad4.x);
            s_e[1][tid] = lrelu_f(av.y + ad4.y);
            s_e[2][tid] = lrelu_f(av.z + ad4.z);
            s_e[3][tid] = lrelu_f(av.w + ad4.w);
        }
        __syncthreads();

        // per-warp (head) chunk max
        float cm = -1e30f;
        for (int i = lane; i < cnt; i += 32) cm = fmaxf(cm, s_e[hh][i]);
#pragma unroll
        for (int o = 16; o; o >>= 1) cm = fmaxf(cm, __shfl_xor_sync(0xffffffffu, cm, o));
        float m_new = fmaxf(m_run, cm);
        float resc = __expf(m_run - m_new);
        s_run *= resc; acc *= resc; m_run = m_new;

        // exp + chunk sum; store w back into s_e (warp-private row)
        float cs = 0.f;
        for (int i = lane; i < cnt; i += 32) {
            float w = __expf(s_e[hh][i] - m_run);
            s_e[hh][i] = w;
            cs += w;
        }
#pragma unroll
        for (int o = 16; o; o >>= 1) cs += __shfl_xor_sync(0xffffffffu, cs, o);
        s_run += cs;
        __syncwarp();

        // gather: serial over chunk edges, x4 unroll for MLP
        int i = 0;
        for (; i + 4 <= cnt; i += 4) {
            int a0 = s_col[i], a1 = s_col[i + 1], a2 = s_col[i + 2], a3 = s_col[i + 3];
            float w0 = s_e[hh][i],     w1 = s_e[hh][i + 1];
            float w2 = s_e[hh][i + 2], w3 = s_e[hh][i + 3];
            float v0 = g_h0[a0 * HID + tid];
            float v1 = g_h0[a1 * HID + tid];
            float v2 = g_h0[a2 * HID + tid];
            float v3 = g_h0[a3 * HID + tid];
            acc += w0 * v0;
            acc += w1 * v1;
            acc += w2 * v2;
            acc += w3 * v3;
        }
        for (; i < cnt; i++) {
            acc += s_e[hh][i] * g_h0[s_col[i] * HID + tid];
        }
    }
    g_h1[n * HID + tid] = acc / (s_run + 1e-16f) + bias_l[tid];
}

// ---------------- batchnorm stats -------------------------------------------
__global__ void k_bnred() {
    __shared__ float ss[256], sq[256];
    int col = threadIdx.x & 127;
    int rp  = threadIdx.x >> 7;
    float s = 0.f, q = 0.f;
    for (int r = blockIdx.x * 2 + rp; r < NN; r += NBNB * 2) {
        float v = g_h1[r * HID + col];
        s += v; q += v * v;
    }
    ss[threadIdx.x] = s; sq[threadIdx.x] = q;
    __syncthreads();
    if (threadIdx.x < 128) {
        g_psum[blockIdx.x * HID + col] = ss[threadIdx.x] + ss[threadIdx.x + 128];
        g_psq[blockIdx.x * HID + col]  = sq[threadIdx.x] + sq[threadIdx.x + 128];
    }
}

__global__ void k_bnstats(const float* __restrict__ gamma, const float* __restrict__ beta) {
    int t = threadIdx.x;   // 128
    float s = 0.f, q = 0.f;
    for (int b = 0; b < NBNB; b++) {
        s += g_psum[b * HID + t];
        q += g_psq[b * HID + t];
    }
    float mean = s / (float)NN;
    float var  = q / (float)NN - mean * mean;
    float rstd = rsqrtf(var + EPSV);
    float scl  = rstd * gamma[t];
    g_scale[t] = scl;
    g_shift[t] = beta[t] - mean * scl;
}

// ---------------- pooling + MLP ---------------------------------------------
__global__ void k_poolzero() {
    int i = blockIdx.x * blockDim.x + threadIdx.x;
    if (i < GG * HID) g_pool[i] = 0.f;
    if (i >= GG * HID && i < GG * HID + GG) g_gcnt[i - GG * HID] = 0;
}

__global__ void k_gcnt(const int* __restrict__ batch) {
    __shared__ int sc[GG];
    if (threadIdx.x < GG) sc[threadIdx.x] = 0;
    __syncthreads();
    int i = blockIdx.x * blockDim.x + threadIdx.x;
    if (i < NN) atomicAdd(&sc[batch[i]], 1);
    __syncthreads();
    if (threadIdx.x < GG && sc[threadIdx.x]) atomicAdd(&g_gcnt[threadIdx.x], sc[threadIdx.x]);
}

__global__ void k_pool(const int* __restrict__ batch) {
    int col = threadIdx.x;     // 128
    int r0  = blockIdx.x * 256;
    if (r0 >= NN) return;
    float scl = g_scale[col], shf = g_shift[col];
    int rend = min(r0 + 256, NN);
    int cur  = batch[r0];
    float acc = 0.f;
    for (int r = r0; r < rend; r++) {
        int g = batch[r];
        if (g != cur) { atomicAdd(&g_pool[cur * HID + col], acc); acc = 0.f; cur = g; }
        float y = g_h1[r * HID + col] * scl + shf;
        acc += silu_f(y);
    }
    atomicAdd(&g_pool[cur * HID + col], acc);
}

__global__ void k_mlp(const float* __restrict__ fc1w, const float* __restrict__ fc1b,
                      const float* __restrict__ fc2w, const float* __restrict__ fc2b,
                      float* __restrict__ out) {
    __shared__ float pm[GG * HID];
    __shared__ float z[GG * 64];
    int tid = threadIdx.x;   // 512
    for (int i = tid; i < GG * HID; i += 512) {
        int g = i >> 7;
        pm[i] = g_pool[i] / fmaxf((float)g_gcnt[g], 1.f);
    }
    __syncthreads();
    for (int idx = tid; idx < GG * 64; idx += 512) {
        int g = idx >> 6, j = idx & 63;
        float a = fc1b[j];
        for (int k = 0; k < HID; k++) a += pm[g * HID + k] * fc1w[k * 64 + j];
        z[idx] = silu_f(a);
    }
    __syncthreads();
    int g = tid >> 5, lane = tid & 31;
    if (g < GG) {
        float s = z[g * 64 + lane] * fc2w[lane] + z[g * 64 + lane + 32] * fc2w[lane + 32];
#pragma unroll
        for (int o = 16; o; o >>= 1) s += __shfl_xor_sync(0xffffffffu, s, o);
        if (lane == 0) {
            float y = s + fc2b[0];
            out[g] = 1.f / (1.f + __expf(-y));
        }
    }
}

// ---------------- launch ----------------------------------------------------
extern "C" void kernel_launch(void* const* d_in, const int* in_sizes, int n_in,
                              void* d_out, int out_size) {
    const float* x     = (const float*)d_in[0];
    const int*   ei    = (const int*)d_in[1];
    const int*   batch = (const int*)d_in[2];
    int p = 3;
    if (n_in > 3 && in_sizes[3] == 1) p = 4;
    const float* W0      = (const float*)d_in[p + 0];
    const float* Ws      = (const float*)d_in[p + 1];
    const float* att_src = (const float*)d_in[p + 2];
    const float* att_dst = (const float*)d_in[p + 3];
    const float* bias    = (const float*)d_in[p + 4];
    const float* gamma   = (const float*)d_in[p + 5];
    const float* beta    = (const float*)d_in[p + 6];
    const float* fc1w    = (const float*)d_in[p + 7];
    const float* fc1b    = (const float*)d_in[p + 8];
    const float* fc2w    = (const float*)d_in[p + 9];
    const float* fc2b    = (const float*)d_in[p + 10];
    float* out = (float*)d_out;

    k_zero_csr<<<(NN + 255) / 256, 256>>>();
    k_hist<<<(ETOT + 255) / 256, 256>>>(ei);
    k_scan_block<<<(NN + 1023) / 1024, 1024>>>();
    k_scan_sums<<<1, 64>>>();
    k_rowptr<<<(NN + 255) / 256, 256>>>();
    k_scatter<<<(ETOT + 255) / 256, 256>>>(ei);

    for (int l = 0; l < 4; l++) {
        if (l == 0) {
            k_gemm0<<<(NN + 63) / 64, 128>>>(x, W0, att_src, att_dst);
        } else {
            k_gemm128<<<(NN + 127) / 128, 256>>>(Ws + (l - 1) * HID * HID,
                                                 att_src + l * HH * CC,
                                                 att_dst + l * HH * CC);
        }
        k_agg<<<NN, 128>>>(bias + l * HID);
        k_bnred<<<NBNB, 256>>>();
        k_bnstats<<<1, 128>>>(gamma + l * HID, beta + l * HID);
    }

    k_poolzero<<<(GG * HID + GG + 255) / 256, 256>>>();
    k_gcnt<<<(NN + 255) / 256, 256>>>(batch);
    k_pool<<<(NN + 255) / 256, 128>>>(batch);
    k_mlp<<<1, 512>>>(fc1w, fc1b, fc2w, fc2b, out);
}

// round 5
// speedup vs baseline: 1.4246x; 1.1690x over previous
#include <cuda_runtime.h>
#include <math.h>

#define NN   50000
#define EE   800000
#define ETOT (EE + NN)
#define HID  128
#define HH   4
#define CC   32
#define GG   16
#define NEG  0.2f
#define EPSV 1e-5f
#define NBNB 256
#define ECHUNK 128

// ---------------- scratch ----------------------------------------------------
__device__ float g_h0[NN * HID];
__device__ float g_h1[NN * HID];
__device__ float g_as[NN * HH];
__device__ float g_ad[NN * HH];
__device__ int   g_cnt[NN];
__device__ int   g_cur[NN];
__device__ int   g_incl[NN];
__device__ int   g_rowptr[NN + 1];
__device__ int   g_col[ETOT];
__device__ int   g_bsum[64];
__device__ float g_psum[NBNB * HID], g_psq[NBNB * HID];
__device__ float g_scale[HID], g_shift[HID];
__device__ float g_pool[GG * HID];
__device__ int   g_gcnt[GG];
__device__ unsigned g_bnctr;

__device__ __forceinline__ float silu_f(float y) { return y / (1.f + __expf(-y)); }
__device__ __forceinline__ float lrelu_f(float a) { return (a > 0.f) ? a : NEG * a; }

__device__ __forceinline__ unsigned f2tf(float f) {
    unsigned r; asm("cvt.rna.tf32.f32 %0, %1;" : "=r"(r) : "f"(f)); return r;
}
__device__ __forceinline__ void mma_tf32(float4& c,
    unsigned a0, unsigned a1, unsigned a2, unsigned a3, unsigned b0, unsigned b1) {
    asm("mma.sync.aligned.m16n8k8.row.col.f32.tf32.tf32.f32 "
        "{%0,%1,%2,%3},{%4,%5,%6,%7},{%8,%9},{%0,%1,%2,%3};"
        : "+f"(c.x), "+f"(c.y), "+f"(c.z), "+f"(c.w)
        : "r"(a0), "r"(a1), "r"(a2), "r"(a3), "r"(b0), "r"(b1));
}

// ---------------- CSR build -------------------------------------------------
__global__ void k_zero_csr() {
    int i = blockIdx.x * blockDim.x + threadIdx.x;
    if (i < NN) { g_cnt[i] = 0; g_cur[i] = 0; }
}

__global__ void k_hist(const int* __restrict__ ei) {
    int e = blockIdx.x * blockDim.x + threadIdx.x;
    if (e >= ETOT) return;
    int d = (e < EE) ? ei[EE + e] : (e - EE);
    atomicAdd(&g_cnt[d], 1);
}

__global__ void k_scan_block() {
    __shared__ int s[1024];
    int i = blockIdx.x * 1024 + threadIdx.x;
    int v = (i < NN) ? g_cnt[i] : 0;
    s[threadIdx.x] = v;
    __syncthreads();
    for (int off = 1; off < 1024; off <<= 1) {
        int t = (threadIdx.x >= off) ? s[threadIdx.x - off] : 0;
        __syncthreads();
        s[threadIdx.x] += t;
        __syncthreads();
    }
    if (i < NN) g_incl[i] = s[threadIdx.x];
    if (threadIdx.x == 1023) g_bsum[blockIdx.x] = s[1023];
}

__global__ void k_scan_sums() {
    __shared__ int s[64];
    int t = threadIdx.x;
    const int nb = (NN + 1023) / 1024;
    int v = (t < nb) ? g_bsum[t] : 0;
    s[t] = v;
    __syncthreads();
    for (int off = 1; off < 64; off <<= 1) {
        int u = (t >= off) ? s[t - off] : 0;
        __syncthreads();
        s[t] += u;
        __syncthreads();
    }
    g_bsum[t] = s[t] - v;
}

__global__ void k_rowptr() {
    int i = blockIdx.x * blockDim.x + threadIdx.x;
    if (i < NN) g_rowptr[i] = g_incl[i] - g_cnt[i] + g_bsum[i >> 10];
    if (i == 0) g_rowptr[NN] = ETOT;
}

__global__ void k_scatter(const int* __restrict__ ei) {
    int e = blockIdx.x * blockDim.x + threadIdx.x;
    if (e >= ETOT) return;
    int s, d;
    if (e < EE) { s = ei[e]; d = ei[EE + e]; }
    else        { s = e - EE; d = s; }
    int pos = g_rowptr[d] + atomicAdd(&g_cur[d], 1);
    g_col[pos] = s;
}

// ---------------- layer-0 GEMM with fused alpha ------------------------------
__global__ void k_gemm0(const float* __restrict__ X, const float* __restrict__ W0,
                        const float* __restrict__ asrc, const float* __restrict__ adst) {
    __shared__ float w[5 * HID];
    __shared__ float xs[64 * 5];
    int tid = threadIdx.x;   // 128
    int hh = tid >> 5, lane = tid & 31;
    for (int i = tid; i < 5 * HID; i += 128) w[i] = W0[i];
    int r0 = blockIdx.x * 64;
    int nr = min(64, NN - r0);
    for (int i = tid; i < nr * 5; i += 128) xs[i] = X[r0 * 5 + i];
    __syncthreads();
    float avs = asrc[tid], avd = adst[tid];
    for (int rr = 0; rr < nr; rr++) {
        float a = 0.f;
#pragma unroll
        for (int k = 0; k < 5; k++) a += xs[rr * 5 + k] * w[k * HID + tid];
        g_h0[(r0 + rr) * HID + tid] = a;
        float s1 = a * avs, s2 = a * avd;
#pragma unroll
        for (int o = 16; o; o >>= 1) {
            s1 += __shfl_xor_sync(0xffffffffu, s1, o);
            s2 += __shfl_xor_sync(0xffffffffu, s2, o);
        }
        if (lane == 0) {
            g_as[(r0 + rr) * HH + hh] = s1;
            g_ad[(r0 + rr) * HH + hh] = s2;
        }
    }
}

// ---------------- layers 1..3: 3xTF32 tensor-core GEMM -----------------------
// h0 = silu(bn(g_h1)) @ B. 128x128 block, 8 warps (2m x 4n), warp tile 64x32.
// Alpha epilogue: warp wn owns head wn's 32 cols -> quad-reduce, direct store.
__global__ __launch_bounds__(256) void k_gemm128(
    const float* __restrict__ B,
    const float* __restrict__ asrc, const float* __restrict__ adst)
{
    __shared__ float As[8][132];
    __shared__ float Bs[8][132];
    __shared__ float sc[HID], sh[HID], sas[HID], sad[HID];
    int tid  = threadIdx.x;
    int lane = tid & 31, warp = tid >> 5;
    int wm = warp >> 2, wn = warp & 3;
    int wr0 = wm * 64, wc0 = wn * 32;
    int row0 = blockIdx.x * 128;
    if (tid < HID) {
        sc[tid] = g_scale[tid]; sh[tid] = g_shift[tid];
        sas[tid] = asrc[tid];   sad[tid] = adst[tid];
    }
    int ar = tid >> 1, akq = (tid & 1) * 4;
    int arow = row0 + ar;
    int bk = tid >> 5, bc = (tid & 31) * 4;
    __syncthreads();

    float4 acc[4][4];
#pragma unroll
    for (int mi = 0; mi < 4; mi++)
#pragma unroll
        for (int ni = 0; ni < 4; ni++) acc[mi][ni] = make_float4(0.f, 0.f, 0.f, 0.f);

    // prologue: tile 0
    float4 va = (arow < NN) ? *(const float4*)&g_h1[arow * HID + akq]
                            : make_float4(0.f, 0.f, 0.f, 0.f);
    float4 vb = *(const float4*)&B[bk * HID + bc];
    {
        float vv[4] = {va.x, va.y, va.z, va.w};
#pragma unroll
        for (int q = 0; q < 4; q++)
            As[akq + q][ar] = silu_f(vv[q] * sc[akq + q] + sh[akq + q]);
        *(float4*)&Bs[bk][bc] = vb;
    }
    __syncthreads();

    int kA = lane & 3;
    int gq = lane >> 2;

    for (int k0 = 0; k0 < 128; k0 += 8) {
        if (k0 + 8 < 128) {
            va = (arow < NN) ? *(const float4*)&g_h1[arow * HID + k0 + 8 + akq]
                             : make_float4(0.f, 0.f, 0.f, 0.f);
            vb = *(const float4*)&B[(k0 + 8 + bk) * HID + bc];
        }
        // B fragments (hi/lo) for the 4 n-tiles
        unsigned bh[4][2], bl[4][2];
#pragma unroll
        for (int ni = 0; ni < 4; ni++) {
            float b0f = Bs[kA][wc0 + ni * 8 + gq];
            float b1f = Bs[kA + 4][wc0 + ni * 8 + gq];
            bh[ni][0] = f2tf(b0f); bl[ni][0] = f2tf(b0f - __uint_as_float(bh[ni][0]));
            bh[ni][1] = f2tf(b1f); bl[ni][1] = f2tf(b1f - __uint_as_float(bh[ni][1]));
        }
#pragma unroll
        for (int mi = 0; mi < 4; mi++) {
            int rg = wr0 + mi * 16 + gq;
            float a0f = As[kA][rg],     a1f = As[kA][rg + 8];
            float a2f = As[kA + 4][rg], a3f = As[kA + 4][rg + 8];
            unsigned ah0 = f2tf(a0f), ah1 = f2tf(a1f), ah2 = f2tf(a2f), ah3 = f2tf(a3f);
            unsigned al0 = f2tf(a0f - __uint_as_float(ah0));
            unsigned al1 = f2tf(a1f - __uint_as_float(ah1));
            unsigned al2 = f2tf(a2f - __uint_as_float(ah2));
            unsigned al3 = f2tf(a3f - __uint_as_float(ah3));
#pragma unroll
            for (int ni = 0; ni < 4; ni++) {
                mma_tf32(acc[mi][ni], ah0, ah1, ah2, ah3, bh[ni][0], bh[ni][1]);
                mma_tf32(acc[mi][ni], ah0, ah1, ah2, ah3, bl[ni][0], bl[ni][1]);
                mma_tf32(acc[mi][ni], al0, al1, al2, al3, bh[ni][0], bh[ni][1]);
            }
        }
        __syncthreads();
        if (k0 + 8 < 128) {
            float vv[4] = {va.x, va.y, va.z, va.w};
#pragma unroll
            for (int q = 0; q < 4; q++) {
                int k = k0 + 8 + akq + q;
                As[akq + q][ar] = silu_f(vv[q] * sc[k] + sh[k]);
            }
            *(float4*)&Bs[bk][bc] = vb;
            __syncthreads();
        }
    }

    // epilogue: store C + per-head alpha (this warp's cols = head wn)
    float ps[8], pd[8];
#pragma unroll
    for (int i = 0; i < 8; i++) { ps[i] = 0.f; pd[i] = 0.f; }
#pragma unroll
    for (int mi = 0; mi < 4; mi++) {
        int r1 = row0 + wr0 + mi * 16 + gq;
        int r2 = r1 + 8;
#pragma unroll
        for (int ni = 0; ni < 4; ni++) {
            float4 c = acc[mi][ni];
            int colb = wc0 + ni * 8 + (lane & 3) * 2;
            ps[mi * 2]     += c.x * sas[colb] + c.y * sas[colb + 1];
            pd[mi * 2]     += c.x * sad[colb] + c.y * sad[colb + 1];
            ps[mi * 2 + 1] += c.z * sas[colb] + c.w * sas[colb + 1];
            pd[mi * 2 + 1] += c.z * sad[colb] + c.w * sad[colb + 1];
            if (r1 < NN) *(float2*)&g_h0[r1 * HID + colb] = make_float2(c.x, c.y);
            if (r2 < NN) *(float2*)&g_h0[r2 * HID + colb] = make_float2(c.z, c.w);
        }
    }
#pragma unroll
    for (int i = 0; i < 8; i++) {
        ps[i] += __shfl_xor_sync(0xffffffffu, ps[i], 1);
        ps[i] += __shfl_xor_sync(0xffffffffu, ps[i], 2);
        pd[i] += __shfl_xor_sync(0xffffffffu, pd[i], 1);
        pd[i] += __shfl_xor_sync(0xffffffffu, pd[i], 2);
    }
    if ((lane & 3) == 0) {
#pragma unroll
        for (int mi = 0; mi < 4; mi++) {
#pragma unroll
            for (int half = 0; half < 2; half++) {
                int r = row0 + wr0 + mi * 16 + half * 8 + gq;
                if (r < NN) {
                    g_as[r * HH + wn] = ps[mi * 2 + half];
                    g_ad[r * HH + wn] = pd[mi * 2 + half];
                }
            }
        }
    }
}

// ---------------- aggregation: block-per-node, SMEM-staged weights ----------
__global__ __launch_bounds__(128, 12) void k_agg(const float* __restrict__ bias_l) {
    __shared__ int   s_col[ECHUNK];
    __shared__ float s_e[HH][ECHUNK];
    int n = blockIdx.x;
    int tid = threadIdx.x;
    int hh = tid >> 5, lane = tid & 31;
    int beg = g_rowptr[n], end = g_rowptr[n + 1];
    float4 ad4 = *(const float4*)&g_ad[n * HH];

    float m_run = -1e30f, s_run = 0.f, acc = 0.f;

    for (int c0 = beg; c0 < end; c0 += ECHUNK) {
        int cnt = min(ECHUNK, end - c0);
        __syncthreads();
        if (tid < cnt) {
            int s = g_col[c0 + tid];
            s_col[tid] = s;
            float4 av = *(const float4*)&g_as[s * HH];
            s_e[0][tid] = lrelu_f(av.x + ad4.x);
            s_e[1][tid] = lrelu_f(av.y + ad4.y);
            s_e[2][tid] = lrelu_f(av.z + ad4.z);
            s_e[3][tid] = lrelu_f(av.w + ad4.w);
        }
        __syncthreads();

        float cm = -1e30f;
        for (int i = lane; i < cnt; i += 32) cm = fmaxf(cm, s_e[hh][i]);
#pragma unroll
        for (int o = 16; o; o >>= 1) cm = fmaxf(cm, __shfl_xor_sync(0xffffffffu, cm, o));
        float m_new = fmaxf(m_run, cm);
        float resc = __expf(m_run - m_new);
        s_run *= resc; acc *= resc; m_run = m_new;

        float cs = 0.f;
        for (int i = lane; i < cnt; i += 32) {
            float w = __expf(s_e[hh][i] - m_run);
            s_e[hh][i] = w;
            cs += w;
        }
#pragma unroll
        for (int o = 16; o; o >>= 1) cs += __shfl_xor_sync(0xffffffffu, cs, o);
        s_run += cs;
        __syncwarp();

        int i = 0;
        for (; i + 4 <= cnt; i += 4) {
            int a0 = s_col[i], a1 = s_col[i + 1], a2 = s_col[i + 2], a3 = s_col[i + 3];
            float w0 = s_e[hh][i],     w1 = s_e[hh][i + 1];
            float w2 = s_e[hh][i + 2], w3 = s_e[hh][i + 3];
            float v0 = g_h0[a0 * HID + tid];
            float v1 = g_h0[a1 * HID + tid];
            float v2 = g_h0[a2 * HID + tid];
            float v3 = g_h0[a3 * HID + tid];
            acc += w0 * v0;
            acc += w1 * v1;
            acc += w2 * v2;
            acc += w3 * v3;
        }
        for (; i < cnt; i++) {
            acc += s_e[hh][i] * g_h0[s_col[i] * HID + tid];
        }
    }
    g_h1[n * HID + tid] = acc / (s_run + 1e-16f) + bias_l[tid];
}

// ---------------- fused batchnorm stats (single kernel) ----------------------
__global__ void k_bn(const float* __restrict__ gamma, const float* __restrict__ beta) {
    __shared__ float ss[256], sq[256];
    __shared__ unsigned s_done;
    int col = threadIdx.x & 127;
    int rp  = threadIdx.x >> 7;
    float s = 0.f, q = 0.f;
    for (int r = blockIdx.x * 2 + rp; r < NN; r += NBNB * 2) {
        float v = g_h1[r * HID + col];
        s += v; q += v * v;
    }
    ss[threadIdx.x] = s; sq[threadIdx.x] = q;
    __syncthreads();
    if (threadIdx.x < 128) {
        g_psum[blockIdx.x * HID + col] = ss[threadIdx.x] + ss[threadIdx.x + 128];
        g_psq[blockIdx.x * HID + col]  = sq[threadIdx.x] + sq[threadIdx.x + 128];
    }
    __threadfence();
    __syncthreads();
    if (threadIdx.x == 0) s_done = atomicAdd(&g_bnctr, 1u);
    __syncthreads();
    if (s_done == NBNB - 1) {
        // last block: reduce partials. 256 threads: col x half
        int t = threadIdx.x;
        int c = t & 127, hb = t >> 7;
        float rs = 0.f, rq = 0.f;
        for (int b = hb * (NBNB / 2); b < (hb + 1) * (NBNB / 2); b += 4) {
            float s0 = g_psum[b * HID + c]       + g_psum[(b + 1) * HID + c];
            float s1 = g_psum[(b + 2) * HID + c] + g_psum[(b + 3) * HID + c];
            float q0 = g_psq[b * HID + c]        + g_psq[(b + 1) * HID + c];
            float q1 = g_psq[(b + 2) * HID + c]  + g_psq[(b + 3) * HID + c];
            rs += s0 + s1; rq += q0 + q1;
        }
        ss[t] = rs; sq[t] = rq;
        __syncthreads();
        if (t < 128) {
            float sum = ss[t] + ss[t + 128];
            float sqq = sq[t] + sq[t + 128];
            float mean = sum / (float)NN;
            float var  = sqq / (float)NN - mean * mean;
            float rstd = rsqrtf(var + EPSV);
            float scl  = rstd * gamma[t];
            g_scale[t] = scl;
            g_shift[t] = beta[t] - mean * scl;
        }
        if (t == 0) g_bnctr = 0;
    }
}

// ---------------- pooling + MLP ---------------------------------------------
__global__ void k_poolzero() {
    int i = blockIdx.x * blockDim.x + threadIdx.x;
    if (i < GG * HID) g_pool[i] = 0.f;
    if (i >= GG * HID && i < GG * HID + GG) g_gcnt[i - GG * HID] = 0;
}

// batch sorted -> running accumulator; BN+SiLU of layer 3 fused; counts fused
__global__ void k_pool(const int* __restrict__ batch) {
    int col = threadIdx.x;     // 128
    int r0  = blockIdx.x * 256;
    if (r0 >= NN) return;
    float scl = g_scale[col], shf = g_shift[col];
    int rend = min(r0 + 256, NN);
    int cur  = batch[r0];
    float acc = 0.f;
    int cnt = 0;
    for (int r = r0; r < rend; r++) {
        int g = batch[r];
        if (g != cur) {
            atomicAdd(&g_pool[cur * HID + col], acc);
            if (col == 0) atomicAdd(&g_gcnt[cur], cnt);
            acc = 0.f; cnt = 0; cur = g;
        }
        float y = g_h1[r * HID + col] * scl + shf;
        acc += silu_f(y);
        cnt++;
    }
    atomicAdd(&g_pool[cur * HID + col], acc);
    if (col == 0) atomicAdd(&g_gcnt[cur], cnt);
}

__global__ void k_mlp(const float* __restrict__ fc1w, const float* __restrict__ fc1b,
                      const float* __restrict__ fc2w, const float* __restrict__ fc2b,
                      float* __restrict__ out) {
    __shared__ float pm[GG * HID];
    __shared__ float z[GG * 64];
    int tid = threadIdx.x;   // 512
    for (int i = tid; i < GG * HID; i += 512) {
        int g = i >> 7;
        pm[i] = g_pool[i] / fmaxf((float)g_gcnt[g], 1.f);
    }
    __syncthreads();
    for (int idx = tid; idx < GG * 64; idx += 512) {
        int g = idx >> 6, j = idx & 63;
        float a = fc1b[j];
        for (int k = 0; k < HID; k++) a += pm[g * HID + k] * fc1w[k * 64 + j];
        z[idx] = silu_f(a);
    }
    __syncthreads();
    int g = tid >> 5, lane = tid & 31;
    if (g < GG) {
        float s = z[g * 64 + lane] * fc2w[lane] + z[g * 64 + lane + 32] * fc2w[lane + 32];
#pragma unroll
        for (int o = 16; o; o >>= 1) s += __shfl_xor_sync(0xffffffffu, s, o);
        if (lane == 0) {
            float y = s + fc2b[0];
            out[g] = 1.f / (1.f + __expf(-y));
        }
    }
}

// ---------------- launch ----------------------------------------------------
extern "C" void kernel_launch(void* const* d_in, const int* in_sizes, int n_in,
                              void* d_out, int out_size) {
    const float* x     = (const float*)d_in[0];
    const int*   ei    = (const int*)d_in[1];
    const int*   batch = (const int*)d_in[2];
    int p = 3;
    if (n_in > 3 && in_sizes[3] == 1) p = 4;
    const float* W0      = (const float*)d_in[p + 0];
    const float* Ws      = (const float*)d_in[p + 1];
    const float* att_src = (const float*)d_in[p + 2];
    const float* att_dst = (const float*)d_in[p + 3];
    const float* bias    = (const float*)d_in[p + 4];
    const float* gamma   = (const float*)d_in[p + 5];
    const float* beta    = (const float*)d_in[p + 6];
    const float* fc1w    = (const float*)d_in[p + 7];
    const float* fc1b    = (const float*)d_in[p + 8];
    const float* fc2w    = (const float*)d_in[p + 9];
    const float* fc2b    = (const float*)d_in[p + 10];
    float* out = (float*)d_out;

    k_zero_csr<<<(NN + 255) / 256, 256>>>();
    k_hist<<<(ETOT + 255) / 256, 256>>>(ei);
    k_scan_block<<<(NN + 1023) / 1024, 1024>>>();
    k_scan_sums<<<1, 64>>>();
    k_rowptr<<<(NN + 255) / 256, 256>>>();
    k_scatter<<<(ETOT + 255) / 256, 256>>>(ei);

    for (int l = 0; l < 4; l++) {
        if (l == 0) {
            k_gemm0<<<(NN + 63) / 64, 128>>>(x, W0, att_src, att_dst);
        } else {
            k_gemm128<<<(NN + 127) / 128, 256>>>(Ws + (l - 1) * HID * HID,
                                                 att_src + l * HH * CC,
                                                 att_dst + l * HH * CC);
        }
        k_agg<<<NN, 128>>>(bias + l * HID);
        k_bn<<<NBNB, 256>>>(gamma + l * HID, beta + l * HID);
    }

    k_poolzero<<<(GG * HID + GG + 255) / 256, 256>>>();
    k_pool<<<(NN + 255) / 256, 128>>>(batch);
    k_mlp<<<1, 512>>>(fc1w, fc1b, fc2w, fc2b, out);
}

// round 7
// speedup vs baseline: 1.4527x; 1.0197x over previous
#include <cuda_runtime.h>
#include <math.h>

#define NN   50000
#define EE   800000
#define ETOT (EE + NN)
#define HID  128
#define HH   4
#define CC   32
#define GG   16
#define NEG  0.2f
#define EPSV 1e-5f
#define NBNB 256
#define ECHUNK 128

// ---------------- scratch ----------------------------------------------------
__device__ float g_h0[NN * HID];
__device__ float g_h1[NN * HID];
__device__ float g_as[NN * HH];
__device__ float g_ad[NN * HH];
__device__ int   g_cnt[NN];
__device__ int   g_cur[NN];
__device__ int   g_incl[NN];
__device__ int   g_rowptr[NN + 1];
__device__ int   g_col[ETOT];
__device__ int   g_bsum[64];
__device__ float g_psum[NBNB * HID], g_psq[NBNB * HID];
__device__ float g_scale[HID], g_shift[HID];
__device__ float g_pool[GG * HID];
__device__ int   g_gcnt[GG];
__device__ unsigned g_bnctr;

__device__ __forceinline__ float silu_f(float y) { return y / (1.f + __expf(-y)); }
__device__ __forceinline__ float lrelu_f(float a) { return (a > 0.f) ? a : NEG * a; }

__device__ __forceinline__ unsigned f2tf(float f) {
    unsigned r; asm("cvt.rna.tf32.f32 %0, %1;" : "=r"(r) : "f"(f)); return r;
}
__device__ __forceinline__ void mma_tf32(float4& c,
    unsigned a0, unsigned a1, unsigned a2, unsigned a3, unsigned b0, unsigned b1) {
    asm("mma.sync.aligned.m16n8k8.row.col.f32.tf32.tf32.f32 "
        "{%0,%1,%2,%3},{%4,%5,%6,%7},{%8,%9},{%0,%1,%2,%3};"
        : "+f"(c.x), "+f"(c.y), "+f"(c.z), "+f"(c.w)
        : "r"(a0), "r"(a1), "r"(a2), "r"(a3), "r"(b0), "r"(b1));
}

// ---------------- CSR build -------------------------------------------------
__global__ void k_zero_csr() {
    int i = blockIdx.x * blockDim.x + threadIdx.x;
    if (i < NN) { g_cnt[i] = 0; g_cur[i] = 0; }
}

__global__ void k_hist(const int* __restrict__ ei) {
    int e = blockIdx.x * blockDim.x + threadIdx.x;
    if (e >= ETOT) return;
    int d = (e < EE) ? ei[EE + e] : (e - EE);
    atomicAdd(&g_cnt[d], 1);
}

__global__ void k_scan_block() {
    __shared__ int s[1024];
    int i = blockIdx.x * 1024 + threadIdx.x;
    int v = (i < NN) ? g_cnt[i] : 0;
    s[threadIdx.x] = v;
    __syncthreads();
    for (int off = 1; off < 1024; off <<= 1) {
        int t = (threadIdx.x >= off) ? s[threadIdx.x - off] : 0;
        __syncthreads();
        s[threadIdx.x] += t;
        __syncthreads();
    }
    if (i < NN) g_incl[i] = s[threadIdx.x];
    if (threadIdx.x == 1023) g_bsum[blockIdx.x] = s[1023];
}

__global__ void k_scan_sums() {
    __shared__ int s[64];
    int t = threadIdx.x;
    const int nb = (NN + 1023) / 1024;
    int v = (t < nb) ? g_bsum[t] : 0;
    s[t] = v;
    __syncthreads();
    for (int off = 1; off < 64; off <<= 1) {
        int u = (t >= off) ? s[t - off] : 0;
        __syncthreads();
        s[t] += u;
        __syncthreads();
    }
    g_bsum[t] = s[t] - v;
}

__global__ void k_rowptr() {
    int i = blockIdx.x * blockDim.x + threadIdx.x;
    if (i < NN) g_rowptr[i] = g_incl[i] - g_cnt[i] + g_bsum[i >> 10];
    if (i == 0) g_rowptr[NN] = ETOT;
}

__global__ void k_scatter(const int* __restrict__ ei) {
    int e = blockIdx.x * blockDim.x + threadIdx.x;
    if (e >= ETOT) return;
    int s, d;
    if (e < EE) { s = ei[e]; d = ei[EE + e]; }
    else        { s = e - EE; d = s; }
    int pos = g_rowptr[d] + atomicAdd(&g_cur[d], 1);
    g_col[pos] = s;
}

// ---------------- layer-0 GEMM with fused alpha ------------------------------
__global__ void k_gemm0(const float* __restrict__ X, const float* __restrict__ W0,
                        const float* __restrict__ asrc, const float* __restrict__ adst) {
    __shared__ float w[5 * HID];
    __shared__ float xs[64 * 5];
    int tid = threadIdx.x;   // 128
    int hh = tid >> 5, lane = tid & 31;
    for (int i = tid; i < 5 * HID; i += 128) w[i] = W0[i];
    int r0 = blockIdx.x * 64;
    int nr = min(64, NN - r0);
    for (int i = tid; i < nr * 5; i += 128) xs[i] = X[r0 * 5 + i];
    __syncthreads();
    float avs = asrc[tid], avd = adst[tid];
    for (int rr = 0; rr < nr; rr++) {
        float a = 0.f;
#pragma unroll
        for (int k = 0; k < 5; k++) a += xs[rr * 5 + k] * w[k * HID + tid];
        g_h0[(r0 + rr) * HID + tid] = a;
        float s1 = a * avs, s2 = a * avd;
#pragma unroll
        for (int o = 16; o; o >>= 1) {
            s1 += __shfl_xor_sync(0xffffffffu, s1, o);
            s2 += __shfl_xor_sync(0xffffffffu, s2, o);
        }
        if (lane == 0) {
            g_as[(r0 + rr) * HH + hh] = s1;
            g_ad[(r0 + rr) * HH + hh] = s2;
        }
    }
}

// ---------------- layers 1..3: 3xTF32 tensor-core GEMM -----------------------
__global__ __launch_bounds__(256) void k_gemm128(
    const float* __restrict__ B,
    const float* __restrict__ asrc, const float* __restrict__ adst)
{
    __shared__ float As[8][132];
    __shared__ float Bs[8][132];
    __shared__ float sc[HID], sh[HID], sas[HID], sad[HID];
    int tid  = threadIdx.x;
    int lane = tid & 31, warp = tid >> 5;
    int wm = warp >> 2, wn = warp & 3;
    int wr0 = wm * 64, wc0 = wn * 32;
    int row0 = blockIdx.x * 128;
    if (tid < HID) {
        sc[tid] = g_scale[tid]; sh[tid] = g_shift[tid];
        sas[tid] = asrc[tid];   sad[tid] = adst[tid];
    }
    int ar = tid >> 1, akq = (tid & 1) * 4;
    int arow = row0 + ar;
    int bk = tid >> 5, bc = (tid & 31) * 4;
    __syncthreads();

    float4 acc[4][4];
#pragma unroll
    for (int mi = 0; mi < 4; mi++)
#pragma unroll
        for (int ni = 0; ni < 4; ni++) acc[mi][ni] = make_float4(0.f, 0.f, 0.f, 0.f);

    float4 va = (arow < NN) ? *(const float4*)&g_h1[arow * HID + akq]
                            : make_float4(0.f, 0.f, 0.f, 0.f);
    float4 vb = *(const float4*)&B[bk * HID + bc];
    {
        float vv[4] = {va.x, va.y, va.z, va.w};
#pragma unroll
        for (int q = 0; q < 4; q++)
            As[akq + q][ar] = silu_f(vv[q] * sc[akq + q] + sh[akq + q]);
        *(float4*)&Bs[bk][bc] = vb;
    }
    __syncthreads();

    int kA = lane & 3;
    int gq = lane >> 2;

    for (int k0 = 0; k0 < 128; k0 += 8) {
        if (k0 + 8 < 128) {
            va = (arow < NN) ? *(const float4*)&g_h1[arow * HID + k0 + 8 + akq]
                             : make_float4(0.f, 0.f, 0.f, 0.f);
            vb = *(const float4*)&B[(k0 + 8 + bk) * HID + bc];
        }
        unsigned bh[4][2], bl[4][2];
#pragma unroll
        for (int ni = 0; ni < 4; ni++) {
            float b0f = Bs[kA][wc0 + ni * 8 + gq];
            float b1f = Bs[kA + 4][wc0 + ni * 8 + gq];
            bh[ni][0] = f2tf(b0f); bl[ni][0] = f2tf(b0f - __uint_as_float(bh[ni][0]));
            bh[ni][1] = f2tf(b1f); bl[ni][1] = f2tf(b1f - __uint_as_float(bh[ni][1]));
        }
#pragma unroll
        for (int mi = 0; mi < 4; mi++) {
            int rg = wr0 + mi * 16 + gq;
            float a0f = As[kA][rg],     a1f = As[kA][rg + 8];
            float a2f = As[kA + 4][rg], a3f = As[kA + 4][rg + 8];
            unsigned ah0 = f2tf(a0f), ah1 = f2tf(a1f), ah2 = f2tf(a2f), ah3 = f2tf(a3f);
            unsigned al0 = f2tf(a0f - __uint_as_float(ah0));
            unsigned al1 = f2tf(a1f - __uint_as_float(ah1));
            unsigned al2 = f2tf(a2f - __uint_as_float(ah2));
            unsigned al3 = f2tf(a3f - __uint_as_float(ah3));
#pragma unroll
            for (int ni = 0; ni < 4; ni++) {
                mma_tf32(acc[mi][ni], ah0, ah1, ah2, ah3, bh[ni][0], bh[ni][1]);
                mma_tf32(acc[mi][ni], ah0, ah1, ah2, ah3, bl[ni][0], bl[ni][1]);
                mma_tf32(acc[mi][ni], al0, al1, al2, al3, bh[ni][0], bh[ni][1]);
            }
        }
        __syncthreads();
        if (k0 + 8 < 128) {
            float vv[4] = {va.x, va.y, va.z, va.w};
#pragma unroll
            for (int q = 0; q < 4; q++) {
                int k = k0 + 8 + akq + q;
                As[akq + q][ar] = silu_f(vv[q] * sc[k] + sh[k]);
            }
            *(float4*)&Bs[bk][bc] = vb;
            __syncthreads();
        }
    }

    float ps[8], pd[8];
#pragma unroll
    for (int i = 0; i < 8; i++) { ps[i] = 0.f; pd[i] = 0.f; }
#pragma unroll
    for (int mi = 0; mi < 4; mi++) {
        int r1 = row0 + wr0 + mi * 16 + gq;
        int r2 = r1 + 8;
#pragma unroll
        for (int ni = 0; ni < 4; ni++) {
            float4 c = acc[mi][ni];
            int colb = wc0 + ni * 8 + (lane & 3) * 2;
            ps[mi * 2]     += c.x * sas[colb] + c.y * sas[colb + 1];
            pd[mi * 2]     += c.x * sad[colb] + c.y * sad[colb + 1];
            ps[mi * 2 + 1] += c.z * sas[colb] + c.w * sas[colb + 1];
            pd[mi * 2 + 1] += c.z * sad[colb] + c.w * sad[colb + 1];
            if (r1 < NN) *(float2*)&g_h0[r1 * HID + colb] = make_float2(c.x, c.y);
            if (r2 < NN) *(float2*)&g_h0[r2 * HID + colb] = make_float2(c.z, c.w);
        }
    }
#pragma unroll
    for (int i = 0; i < 8; i++) {
        ps[i] += __shfl_xor_sync(0xffffffffu, ps[i], 1);
        ps[i] += __shfl_xor_sync(0xffffffffu, ps[i], 2);
        pd[i] += __shfl_xor_sync(0xffffffffu, pd[i], 1);
        pd[i] += __shfl_xor_sync(0xffffffffu, pd[i], 2);
    }
    if ((lane & 3) == 0) {
#pragma unroll
        for (int mi = 0; mi < 4; mi++) {
#pragma unroll
            for (int half = 0; half < 2; half++) {
                int r = row0 + wr0 + mi * 16 + half * 8 + gq;
                if (r < NN) {
                    g_as[r * HH + wn] = ps[mi * 2 + half];
                    g_ad[r * HH + wn] = pd[mi * 2 + half];
                }
            }
        }
    }
}

// ---------------- aggregation: edge-parallel float4 gather -------------------
// block = node. softmax phase: warp = head. gather phase: thread t covers
// edge-group (t>>5) with channels (t&31)*4..+3 via one float4 load per edge.
__global__ __launch_bounds__(128, 12) void k_agg(const float* __restrict__ bias_l) {
    __shared__ int    s_col[ECHUNK];
    __shared__ float  s_e[HH][ECHUNK + 4];
    __shared__ float4 s_red[128];
    __shared__ float  s_resc[HH], s_sum[HH];
    int n = blockIdx.x;
    int tid = threadIdx.x;
    int hh = tid >> 5, lane = tid & 31;
    int eg = tid >> 5;                 // edge group 0..3
    int ch4 = (tid & 31) * 4;          // channel base
    int ghead = (tid & 31) >> 3;       // head owning my channels
    int beg = g_rowptr[n], end = g_rowptr[n + 1];
    float4 ad4 = *(const float4*)&g_ad[n * HH];

    float m_run = -1e30f, s_run = 0.f;
    float4 acc = make_float4(0.f, 0.f, 0.f, 0.f);

    for (int c0 = beg; c0 < end; c0 += ECHUNK) {
        int cnt = min(ECHUNK, end - c0);
        __syncthreads();
        if (tid < cnt) {
            int s = g_col[c0 + tid];
            s_col[tid] = s;
            float4 av = *(const float4*)&g_as[s * HH];
            s_e[0][tid] = lrelu_f(av.x + ad4.x);
            s_e[1][tid] = lrelu_f(av.y + ad4.y);
            s_e[2][tid] = lrelu_f(av.z + ad4.z);
            s_e[3][tid] = lrelu_f(av.w + ad4.w);
        }
        __syncthreads();

        // softmax phase: warp hh owns head hh
        float cm = -1e30f;
        for (int i = lane; i < cnt; i += 32) cm = fmaxf(cm, s_e[hh][i]);
#pragma unroll
        for (int o = 16; o; o >>= 1) cm = fmaxf(cm, __shfl_xor_sync(0xffffffffu, cm, o));
        float m_new = fmaxf(m_run, cm);
        float resc = __expf(m_run - m_new);
        if (lane == 0) s_resc[hh] = resc;
        m_run = m_new;

        float cs = 0.f;
        for (int i = lane; i < cnt; i += 32) {
            float w = __expf(s_e[hh][i] - m_run);
            s_e[hh][i] = w;
            cs += w;
        }
#pragma unroll
        for (int o = 16; o; o >>= 1) cs += __shfl_xor_sync(0xffffffffu, cs, o);
        s_run = s_run * resc + cs;
        __syncthreads();

        // gather phase: edges eg, eg+4, ... with x4 unroll (16 edges in flight)
        float rs = s_resc[ghead];
        acc.x *= rs; acc.y *= rs; acc.z *= rs; acc.w *= rs;
        int i = eg;
        for (; i + 12 < cnt; i += 16) {
            int a0 = s_col[i], a1 = s_col[i + 4], a2 = s_col[i + 8], a3 = s_col[i + 12];
            float w0 = s_e[ghead][i],     w1 = s_e[ghead][i + 4];
            float w2 = s_e[ghead][i + 8], w3 = s_e[ghead][i + 12];
            float4 v0 = *(const float4*)&g_h0[a0 * HID + ch4];
            float4 v1 = *(const float4*)&g_h0[a1 * HID + ch4];
            float4 v2 = *(const float4*)&g_h0[a2 * HID + ch4];
            float4 v3 = *(const float4*)&g_h0[a3 * HID + ch4];
            acc.x += w0 * v0.x; acc.y += w0 * v0.y; acc.z += w0 * v0.z; acc.w += w0 * v0.w;
            acc.x += w1 * v1.x; acc.y += w1 * v1.y; acc.z += w1 * v1.z; acc.w += w1 * v1.w;
            acc.x += w2 * v2.x; acc.y += w2 * v2.y; acc.z += w2 * v2.z; acc.w += w2 * v2.w;
            acc.x += w3 * v3.x; acc.y += w3 * v3.y; acc.z += w3 * v3.z; acc.w += w3 * v3.w;
        }
        for (; i < cnt; i += 4) {
            int a0 = s_col[i];
            float w0 = s_e[ghead][i];
            float4 v0 = *(const float4*)&g_h0[a0 * HID + ch4];
            acc.x += w0 * v0.x; acc.y += w0 * v0.y; acc.z += w0 * v0.z; acc.w += w0 * v0.w;
        }
    }
    if (lane == 0) s_sum[hh] = s_run;
    s_red[tid] = acc;
    __syncthreads();

    if (tid < 32) {
        float4 a = s_red[tid], b = s_red[tid + 32];
        float4 c = s_red[tid + 64], d = s_red[tid + 96];
        float inv = 1.f / (s_sum[tid >> 3] + 1e-16f);
        float4 bi = *(const float4*)&bias_l[tid * 4];
        float4 o;
        o.x = (a.x + b.x + c.x + d.x) * inv + bi.x;
        o.y = (a.y + b.y + c.y + d.y) * inv + bi.y;
        o.z = (a.z + b.z + c.z + d.z) * inv + bi.z;
        o.w = (a.w + b.w + c.w + d.w) * inv + bi.w;
        *(float4*)&g_h1[n * HID + tid * 4] = o;
    }
}

// ---------------- fused batchnorm stats (single kernel) ----------------------
__global__ void k_bn(const float* __restrict__ gamma, const float* __restrict__ beta) {
    __shared__ float ss[256], sq[256];
    __shared__ unsigned s_done;
    int c4 = (threadIdx.x & 31) * 4;
    int rp = threadIdx.x >> 5;       // 0..7
    float4 s4 = make_float4(0.f, 0.f, 0.f, 0.f);
    float4 q4 = make_float4(0.f, 0.f, 0.f, 0.f);
    for (int r = blockIdx.x * 8 + rp; r < NN; r += NBNB * 8) {
        float4 v = *(const float4*)&g_h1[r * HID + c4];
        s4.x += v.x; s4.y += v.y; s4.z += v.z; s4.w += v.w;
        q4.x += v.x * v.x; q4.y += v.y * v.y; q4.z += v.z * v.z; q4.w += v.w * v.w;
    }
    for (int comp = 0; comp < 4; comp++) {
        float sv = comp == 0 ? s4.x : comp == 1 ? s4.y : comp == 2 ? s4.z : s4.w;
        float qv = comp == 0 ? q4.x : comp == 1 ? q4.y : comp == 2 ? q4.z : q4.w;
        ss[threadIdx.x] = sv; sq[threadIdx.x] = qv;
        __syncthreads();
        if (threadIdx.x < 32) {
            float rs = 0.f, rq = 0.f;
#pragma unroll
            for (int g = 0; g < 8; g++) { rs += ss[g * 32 + threadIdx.x]; rq += sq[g * 32 + threadIdx.x]; }
            g_psum[blockIdx.x * HID + threadIdx.x * 4 + comp] = rs;
            g_psq[blockIdx.x * HID + threadIdx.x * 4 + comp]  = rq;
        }
        __syncthreads();
    }
    __threadfence();
    if (threadIdx.x == 0) s_done = atomicAdd(&g_bnctr, 1u);
    __syncthreads();
    if (s_done == NBNB - 1) {
        int t = threadIdx.x;
        int c = t & 127, hb = t >> 7;
        float rs = 0.f, rq = 0.f;
        for (int b = hb * (NBNB / 2); b < (hb + 1) * (NBNB / 2); b += 4) {
            float s0 = g_psum[b * HID + c]       + g_psum[(b + 1) * HID + c];
            float s1 = g_psum[(b + 2) * HID + c] + g_psum[(b + 3) * HID + c];
            float q0 = g_psq[b * HID + c]        + g_psq[(b + 1) * HID + c];
            float q1 = g_psq[(b + 2) * HID + c]  + g_psq[(b + 3) * HID + c];
            rs += s0 + s1; rq += q0 + q1;
        }
        ss[t] = rs; sq[t] = rq;
        __syncthreads();
        if (t < 128) {
            float sum = ss[t] + ss[t + 128];
            float sqq = sq[t] + sq[t + 128];
            float mean = sum / (float)NN;
            float var  = sqq / (float)NN - mean * mean;
            float rstd = rsqrtf(var + EPSV);
            float scl  = rstd * gamma[t];
            g_scale[t] = scl;
            g_shift[t] = beta[t] - mean * scl;
        }
        if (t == 0) g_bnctr = 0;
    }
}

// ---------------- pooling + MLP ---------------------------------------------
__global__ void k_poolzero() {
    int i = blockIdx.x * blockDim.x + threadIdx.x;
    if (i < GG * HID) g_pool[i] = 0.f;
    if (i >= GG * HID && i < GG * HID + GG) g_gcnt[i - GG * HID] = 0;
}

__global__ void k_pool(const int* __restrict__ batch) {
    int col = threadIdx.x;     // 128
    int r0  = blockIdx.x * 256;
    if (r0 >= NN) return;
    float scl = g_scale[col], shf = g_shift[col];
    int rend = min(r0 + 256, NN);
    int cur  = batch[r0];
    float acc = 0.f;
    int cnt = 0;
    for (int r = r0; r < rend; r++) {
        int g = batch[r];
        if (g != cur) {
            atomicAdd(&g_pool[cur * HID + col], acc);
            if (col == 0) atomicAdd(&g_gcnt[cur], cnt);
            acc = 0.f; cnt = 0; cur = g;
        }
        float y = g_h1[r * HID + col] * scl + shf;
        acc += silu_f(y);
        cnt++;
    }
    atomicAdd(&g_pool[cur * HID + col], acc);
    if (col == 0) atomicAdd(&g_gcnt[cur], cnt);
}

__global__ void k_mlp(const float* __restrict__ fc1w, const float* __restrict__ fc1b,
                      const float* __restrict__ fc2w, const float* __restrict__ fc2b,
                      float* __restrict__ out) {
    __shared__ float pm[GG * HID];
    __shared__ float z[GG * 64];
    int tid = threadIdx.x;   // 512
    for (int i = tid; i < GG * HID; i += 512) {
        int g = i >> 7;
        pm[i] = g_pool[i] / fmaxf((float)g_gcnt[g], 1.f);
    }
    __syncthreads();
    for (int idx = tid; idx < GG * 64; idx += 512) {
        int g = idx >> 6, j = idx & 63;
        float a = fc1b[j];
        for (int k = 0; k < HID; k++) a += pm[g * HID + k] * fc1w[k * 64 + j];
        z[idx] = silu_f(a);
    }
    __syncthreads();
    int g = tid >> 5, lane = tid & 31;
    if (g < GG) {
        float s = z[g * 64 + lane] * fc2w[lane] + z[g * 64 + lane + 32] * fc2w[lane + 32];
#pragma unroll
        for (int o = 16; o; o >>= 1) s += __shfl_xor_sync(0xffffffffu, s, o);
        if (lane == 0) {
            float y = s + fc2b[0];
            out[g] = 1.f / (1.f + __expf(-y));
        }
    }
}

// ---------------- launch ----------------------------------------------------
extern "C" void kernel_launch(void* const* d_in, const int* in_sizes, int n_in,
                              void* d_out, int out_size) {
    const float* x     = (const float*)d_in[0];
    const int*   ei    = (const int*)d_in[1];
    const int*   batch = (const int*)d_in[2];
    int p = 3;
    if (n_in > 3 && in_sizes[3] == 1) p = 4;
    const float* W0      = (const float*)d_in[p + 0];
    const float* Ws      = (const float*)d_in[p + 1];
    const float* att_src = (const float*)d_in[p + 2];
    const float* att_dst = (const float*)d_in[p + 3];
    const float* bias    = (const float*)d_in[p + 4];
    const float* gamma   = (const float*)d_in[p + 5];
    const float* beta    = (const float*)d_in[p + 6];
    const float* fc1w    = (const float*)d_in[p + 7];
    const float* fc1b    = (const float*)d_in[p + 8];
    const float* fc2w    = (const float*)d_in[p + 9];
    const float* fc2b    = (const float*)d_in[p + 10];
    float* out = (float*)d_out;

    k_zero_csr<<<(NN + 255) / 256, 256>>>();
    k_hist<<<(ETOT + 255) / 256, 256>>>(ei);
    k_scan_block<<<(NN + 1023) / 1024, 1024>>>();
    k_scan_sums<<<1, 64>>>();
    k_rowptr<<<(NN + 255) / 256, 256>>>();
    k_scatter<<<(ETOT + 255) / 256, 256>>>(ei);

    for (int l = 0; l < 4; l++) {
        if (l == 0) {
            k_gemm0<<<(NN + 63) / 64, 128>>>(x, W0, att_src, att_dst);
        } else {
            k_gemm128<<<(NN + 127) / 128, 256>>>(Ws + (l - 1) * HID * HID,
                                                 att_src + l * HH * CC,
                                                 att_dst + l * HH * CC);
        }
        k_agg<<<NN, 128>>>(bias + l * HID);
        k_bn<<<NBNB, 256>>>(gamma + l * HID, beta + l * HID);
    }

    k_poolzero<<<(GG * HID + GG + 255) / 256, 256>>>();
    k_pool<<<(NN + 255) / 256, 128>>>(batch);
    k_mlp<<<1, 512>>>(fc1w, fc1b, fc2w, fc2b, out);
}